// round 4
// baseline (speedup 1.0000x reference)
#include <cuda_runtime.h>
#include <cuda_bf16.h>
#include <math.h>

// ---------------- problem constants ----------------
constexpr int CB   = 2;
constexpr int CS   = 1024;
constexpr int CH   = 1024;
constexpr int CNH  = 16;
constexpr int CNKV = 4;
constexpr int CDH  = 64;
constexpr int CI   = 4096;
constexpr int CE   = 8;
constexpr int CT   = CB * CS;          // 2048 tokens
constexpr float CEPS = 1e-5f;

// ---------------- device scratch (allocation-free rule: __device__ globals) ----------------
__device__ float g_hnorm[CT * CH];
__device__ float g_q[CT * CNH * CDH];
__device__ float g_k[CT * CNKV * CDH];
__device__ float g_v[CT * CNKV * CDH];
__device__ float g_scores[(long)CB * CNH * CS * CS];   // 134 MB
__device__ float g_attn[CT * CH];
__device__ float g_aproj[CT * CH];
__device__ float g_x[CT * CH];
__device__ float g_h2[CT * CH];
__device__ int   g_topi[CT * 2];
__device__ float g_topw[CT * 2];
__device__ int   g_tok[CE * CT];
__device__ float g_etw[CE * CT];
__device__ int   g_cnt[CE];
__device__ float g_mid1[CT * CI];
__device__ float g_mid2[CT * CI];
__device__ float g_moe[CT * CH];

// ---------------- rmsnorm (optionally + residual) ----------------
__global__ __launch_bounds__(256) void rmsnorm_kernel(
    const float* __restrict__ in, const float* __restrict__ sc,
    const float* __restrict__ resid, float* __restrict__ out)
{
    long row = blockIdx.x;
    const float* x = in + row * CH;
    int tid = threadIdx.x;
    float v[4];
    float ss = 0.f;
#pragma unroll
    for (int u = 0; u < 4; u++) {
        v[u] = x[tid + u * 256];
        ss += v[u] * v[u];
    }
    __shared__ float red[256];
    red[tid] = ss;
    __syncthreads();
    for (int s = 128; s > 0; s >>= 1) {
        if (tid < s) red[tid] += red[tid + s];
        __syncthreads();
    }
    float r = rsqrtf(red[0] * (1.0f / CH) + CEPS);
#pragma unroll
    for (int u = 0; u < 4; u++) {
        int h = tid + u * 256;
        float o = v[u] * r * sc[h];
        if (resid) o += resid[row * CH + h];
        out[row * CH + h] = o;
    }
}

// ---------------- generic 128x128x8 SGEMM, row-major A[MxK] @ B[KxN] -> C[MxN] ----------------
// GATHER: A row m is taken from row_idx[m] of A.
// SCATTER: C row m is written (plain +=, each row unique per call) to row_idx[m], scaled by row_w[m].
// m_count (device): overrides M.
template <bool GATHER, bool SCATTER>
__global__ __launch_bounds__(256) void sgemm_kernel(
    const float* __restrict__ A, const float* __restrict__ B, float* __restrict__ C,
    int M, int N, int K,
    const int* __restrict__ row_idx, const float* __restrict__ row_w,
    const int* __restrict__ m_count)
{
    if (m_count) M = *m_count;
    int row_base = blockIdx.y * 128;
    if (row_base >= M) return;
    int col_base = blockIdx.x * 128;

    __shared__ float As[8][128];
    __shared__ float Bs[8][128];

    int tid = threadIdx.x;
    int arow = tid >> 1;
    int acol = (tid & 1) * 4;
    int brow = tid >> 5;
    int bcol = (tid & 31) << 2;

    int grow = row_base + arow;
    bool arow_valid = grow < M;
    long aoff = 0;
    if (arow_valid) {
        int r = GATHER ? row_idx[grow] : grow;
        aoff = (long)r * K;
    }

    int trow = (tid >> 4) * 8;
    int tcol = (tid & 15) * 8;
    float acc[8][8];
#pragma unroll
    for (int i = 0; i < 8; i++)
#pragma unroll
        for (int j = 0; j < 8; j++) acc[i][j] = 0.f;

    for (int k0 = 0; k0 < K; k0 += 8) {
        float4 av = make_float4(0.f, 0.f, 0.f, 0.f);
        if (arow_valid) av = *(const float4*)(A + aoff + k0 + acol);
        As[acol + 0][arow] = av.x;
        As[acol + 1][arow] = av.y;
        As[acol + 2][arow] = av.z;
        As[acol + 3][arow] = av.w;

        float4 bv = *(const float4*)(B + (long)(k0 + brow) * N + col_base + bcol);
        *(float4*)&Bs[brow][bcol] = bv;
        __syncthreads();

#pragma unroll
        for (int kk = 0; kk < 8; kk++) {
            float4 a0 = *(const float4*)&As[kk][trow];
            float4 a1 = *(const float4*)&As[kk][trow + 4];
            float4 b0 = *(const float4*)&Bs[kk][tcol];
            float4 b1 = *(const float4*)&Bs[kk][tcol + 4];
            float af[8] = {a0.x, a0.y, a0.z, a0.w, a1.x, a1.y, a1.z, a1.w};
            float bf[8] = {b0.x, b0.y, b0.z, b0.w, b1.x, b1.y, b1.z, b1.w};
#pragma unroll
            for (int i = 0; i < 8; i++)
#pragma unroll
                for (int j = 0; j < 8; j++) acc[i][j] += af[i] * bf[j];
        }
        __syncthreads();
    }

#pragma unroll
    for (int i = 0; i < 8; i++) {
        int m = row_base + trow + i;
        if (m >= M) continue;
        if (!SCATTER) {
            float* crow = C + (long)m * N + col_base + tcol;
            float4 c0 = make_float4(acc[i][0], acc[i][1], acc[i][2], acc[i][3]);
            float4 c1 = make_float4(acc[i][4], acc[i][5], acc[i][6], acc[i][7]);
            *(float4*)crow = c0;
            *(float4*)(crow + 4) = c1;
        } else {
            int tk = row_idx[m];
            float w = row_w[m];
            float* crow = C + (long)tk * N + col_base + tcol;
#pragma unroll
            for (int j = 0; j < 8; j++) crow[j] += w * acc[i][j];
        }
    }
}

// ---------------- RoPE on q (16 heads) and k (4 heads) ----------------
__global__ __launch_bounds__(256) void rope_kernel(
    float* __restrict__ q, float* __restrict__ k, const int* __restrict__ pos)
{
    long idx = (long)blockIdx.x * 256 + threadIdx.x;   // token*20heads*32
    if (idx >= (long)CT * 20 * 32) return;
    int d = idx & 31;
    int hh = (int)((idx >> 5) % 20);
    int t = (int)(idx / (32 * 20));
    float p = (float)pos[t];
    float inv = powf(10000.0f, -((float)d) / 32.0f);
    float ang = p * inv;
    float c = cosf(ang), s = sinf(ang);
    float* ptr;
    if (hh < CNH) ptr = q + (long)t * (CNH * CDH) + hh * CDH;
    else          ptr = k + (long)t * (CNKV * CDH) + (hh - CNH) * CDH;
    float x1 = ptr[d], x2 = ptr[d + 32];
    ptr[d]      = x1 * c - x2 * s;
    ptr[d + 32] = x2 * c + x1 * s;
}

// ---------------- attention scores: one 64x64 tile per block, causal tiles only ----------------
__global__ __launch_bounds__(256) void attn_score_kernel(
    const float* __restrict__ q, const float* __restrict__ k, float* __restrict__ scores)
{
    int jt = blockIdx.x, it = blockIdx.y;
    if (jt > it) return;
    int bh = blockIdx.z;
    int b = bh >> 4, h = bh & 15, kv = h >> 2;

    __shared__ float Qs[64][68];   // [d][i]
    __shared__ float Ks[64][68];   // [d][j]
    int tid = threadIdx.x;
#pragma unroll
    for (int l = 0; l < 4; l++) {
        int e = tid + l * 256;
        int r = e >> 4;
        int c = (e & 15) << 2;
        float4 a = *(const float4*)(q + (long)(b * CS + it * 64 + r) * (CNH * CDH) + h * CDH + c);
        Qs[c][r] = a.x; Qs[c + 1][r] = a.y; Qs[c + 2][r] = a.z; Qs[c + 3][r] = a.w;
        float4 bb = *(const float4*)(k + (long)(b * CS + jt * 64 + r) * (CNKV * CDH) + kv * CDH + c);
        Ks[c][r] = bb.x; Ks[c + 1][r] = bb.y; Ks[c + 2][r] = bb.z; Ks[c + 3][r] = bb.w;
    }
    __syncthreads();

    int ti = (tid >> 4) << 2;
    int tj = (tid & 15) << 2;
    float acc[4][4] = {};
#pragma unroll 8
    for (int d = 0; d < 64; d++) {
        float4 a = *(const float4*)&Qs[d][ti];
        float4 bb = *(const float4*)&Ks[d][tj];
        float af[4] = {a.x, a.y, a.z, a.w};
        float bf[4] = {bb.x, bb.y, bb.z, bb.w};
#pragma unroll
        for (int i = 0; i < 4; i++)
#pragma unroll
            for (int j = 0; j < 4; j++) acc[i][j] += af[i] * bf[j];
    }
    const float scale = 0.125f;  // DH^-0.5
#pragma unroll
    for (int i = 0; i < 4; i++) {
        long rbase = ((long)bh * CS + it * 64 + ti + i) * CS + jt * 64 + tj;
#pragma unroll
        for (int j = 0; j < 4; j++) scores[rbase + j] = acc[i][j] * scale;
    }
}

// ---------------- causal masked softmax, in-place on scores; zero-pads tail of diag tile ----------------
__global__ __launch_bounds__(256) void attn_softmax_kernel(
    float* __restrict__ scores, const int* __restrict__ amask)
{
    int i = blockIdx.x, bh = blockIdx.y;
    int b = bh >> 4;
    float* row = scores + ((long)bh * CS + i) * CS;
    int len = i + 1;
    int jceil = ((i >> 6) + 1) << 6;
    int tid = threadIdx.x;
    __shared__ float red[256];

    float mx = -1e30f;
    for (int j = tid; j < len; j += 256) {
        float v = (amask[b * CS + j] > 0) ? row[j] : -1e9f;
        mx = fmaxf(mx, v);
    }
    red[tid] = mx; __syncthreads();
    for (int s = 128; s > 0; s >>= 1) {
        if (tid < s) red[tid] = fmaxf(red[tid], red[tid + s]);
        __syncthreads();
    }
    float M = red[0]; __syncthreads();

    float sum = 0.f;
    for (int j = tid; j < len; j += 256) {
        float v = (amask[b * CS + j] > 0) ? row[j] : -1e9f;
        sum += expf(v - M);
    }
    red[tid] = sum; __syncthreads();
    for (int s = 128; s > 0; s >>= 1) {
        if (tid < s) red[tid] += red[tid + s];
        __syncthreads();
    }
    float inv = 1.0f / red[0];

    for (int j = tid; j < len; j += 256) {
        float v = (amask[b * CS + j] > 0) ? row[j] : -1e9f;
        row[j] = expf(v - M) * inv;
    }
    for (int j = len + tid; j < jceil; j += 256) row[j] = 0.f;
}

// ---------------- PV: out[64 x 64] per (it, bh), looping causal j-tiles ----------------
__global__ __launch_bounds__(256) void attn_pv_kernel(
    const float* __restrict__ probs, const float* __restrict__ v, float* __restrict__ attn)
{
    int it = blockIdx.x;
    int bh = blockIdx.y;
    int b = bh >> 4, h = bh & 15, kv = h >> 2;

    __shared__ float Ps[64][68];  // [j][i]
    __shared__ float Vs[64][68];  // [j][d]
    int tid = threadIdx.x;
    int ti = (tid >> 4) << 2;
    int td = (tid & 15) << 2;
    float acc[4][4] = {};

    for (int jt = 0; jt <= it; jt++) {
#pragma unroll
        for (int l = 0; l < 4; l++) {
            int e = tid + l * 256;
            int r = e >> 4;
            int c = (e & 15) << 2;
            float4 p = *(const float4*)(probs + ((long)bh * CS + it * 64 + r) * CS + jt * 64 + c);
            Ps[c][r] = p.x; Ps[c + 1][r] = p.y; Ps[c + 2][r] = p.z; Ps[c + 3][r] = p.w;
            float4 vv = *(const float4*)(v + (long)(b * CS + jt * 64 + r) * (CNKV * CDH) + kv * CDH + c);
            *(float4*)&Vs[r][c] = vv;
        }
        __syncthreads();
#pragma unroll 8
        for (int jj = 0; jj < 64; jj++) {
            float4 a = *(const float4*)&Ps[jj][ti];
            float4 bb = *(const float4*)&Vs[jj][td];
            float af[4] = {a.x, a.y, a.z, a.w};
            float bf[4] = {bb.x, bb.y, bb.z, bb.w};
#pragma unroll
            for (int i = 0; i < 4; i++)
#pragma unroll
                for (int j = 0; j < 4; j++) acc[i][j] += af[i] * bf[j];
        }
        __syncthreads();
    }
#pragma unroll
    for (int i = 0; i < 4; i++) {
        long rbase = (long)(b * CS + it * 64 + ti + i) * CH + h * CDH + td;
#pragma unroll
        for (int j = 0; j < 4; j++) attn[rbase + j] = acc[i][j];
    }
}

// ---------------- MoE gating: softmax over 8 logits + top-2 ----------------
__global__ __launch_bounds__(128) void gate_kernel(
    const float* __restrict__ h2, const float* __restrict__ gw,
    int* __restrict__ topi, float* __restrict__ topw)
{
    int t = blockIdx.x;
    int tid = threadIdx.x;
    float p[8] = {};
    for (int hh = tid; hh < CH; hh += 128) {
        float x = h2[(long)t * CH + hh];
        const float* g = gw + hh * CE;
#pragma unroll
        for (int e = 0; e < 8; e++) p[e] += x * g[e];
    }
    __shared__ float red[128 * 8];
#pragma unroll
    for (int e = 0; e < 8; e++) red[tid * 8 + e] = p[e];
    __syncthreads();
    for (int s = 64; s > 0; s >>= 1) {
        if (tid < s)
#pragma unroll
            for (int e = 0; e < 8; e++) red[tid * 8 + e] += red[(tid + s) * 8 + e];
        __syncthreads();
    }
    if (tid == 0) {
        float lg[8], pr[8];
        float m = -1e30f;
#pragma unroll
        for (int e = 0; e < 8; e++) { lg[e] = red[e]; m = fmaxf(m, lg[e]); }
        float sum = 0.f;
#pragma unroll
        for (int e = 0; e < 8; e++) { pr[e] = expf(lg[e] - m); sum += pr[e]; }
        float inv = 1.0f / sum;
#pragma unroll
        for (int e = 0; e < 8; e++) pr[e] *= inv;
        int i0 = 0;
#pragma unroll
        for (int e = 1; e < 8; e++) if (pr[e] > pr[i0]) i0 = e;
        int i1 = -1;
#pragma unroll
        for (int e = 0; e < 8; e++) {
            if (e == i0) continue;
            if (i1 < 0 || pr[e] > pr[i1]) i1 = e;
        }
        topi[t * 2] = i0; topi[t * 2 + 1] = i1;
        topw[t * 2] = pr[i0]; topw[t * 2 + 1] = pr[i1];
    }
}

// ---------------- deterministic per-expert token compaction (1 warp per expert) ----------------
__global__ __launch_bounds__(32) void route_kernel(
    const int* __restrict__ topi, const float* __restrict__ topw,
    int* __restrict__ tok, float* __restrict__ etw, int* __restrict__ cnt)
{
    int e = blockIdx.x;
    int lane = threadIdx.x;
    int count = 0;
    for (int base = 0; base < CT; base += 32) {
        int t = base + lane;
        int i0 = topi[t * 2], i1 = topi[t * 2 + 1];
        bool sel = (i0 == e) || (i1 == e);
        float w = (i0 == e) ? topw[t * 2] : topw[t * 2 + 1];
        unsigned m = __ballot_sync(0xFFFFFFFFu, sel);
        int pos = count + __popc(m & ((1u << lane) - 1u));
        if (sel) {
            tok[e * CT + pos] = t;
            etw[e * CT + pos] = w;
        }
        count += __popc(m);
    }
    if (lane == 0) cnt[e] = count;
}

// ---------------- GEGLU: mid1 = gelu_tanh(mid1) * mid2 ----------------
__global__ __launch_bounds__(256) void glu_kernel(
    float* __restrict__ a, const float* __restrict__ b, const int* __restrict__ cnt)
{
    int row = blockIdx.y;
    if (row >= *cnt) return;
    long idx = (long)row * CI + blockIdx.x * 256 + threadIdx.x;
    float x = a[idx];
    float g = 0.5f * x * (1.0f + tanhf(0.7978845608028654f * (x + 0.044715f * x * x * x)));
    a[idx] = g * b[idx];
}

// ---------------- zero fill ----------------
__global__ __launch_bounds__(256) void zero_kernel(float* __restrict__ p)
{
    p[(long)blockIdx.x * 256 + threadIdx.x] = 0.f;
}

// ---------------- host orchestration ----------------
#define SYMADDR(var, ptr) do { void* _p = nullptr; cudaGetSymbolAddress(&_p, var); ptr = (decltype(ptr))_p; } while (0)

extern "C" void kernel_launch(void* const* d_in, const int* in_sizes, int n_in,
                              void* d_out, int out_size)
{
    const float* hidden   = (const float*)d_in[0];
    const int*   amask    = (const int*)d_in[1];
    const int*   posids   = (const int*)d_in[2];
    const float* q_w      = (const float*)d_in[3];
    const float* k_w      = (const float*)d_in[4];
    const float* v_w      = (const float*)d_in[5];
    const float* o_w      = (const float*)d_in[6];
    const float* pre_attn = (const float*)d_in[7];
    const float* post_attn= (const float*)d_in[8];
    const float* pre_moe  = (const float*)d_in[9];
    const float* post_moe = (const float*)d_in[10];
    const float* gate_w   = (const float*)d_in[11];
    const float* w_in     = (const float*)d_in[12];
    const float* w_v      = (const float*)d_in[13];
    const float* w_out    = (const float*)d_in[14];
    float* out = (float*)d_out;

    float *hnorm, *q, *k, *v, *scores, *attn, *aproj, *x, *h2, *mid1, *mid2, *moe, *topw, *etw;
    int *topi, *tok, *cnt;
    SYMADDR(g_hnorm, hnorm); SYMADDR(g_q, q); SYMADDR(g_k, k); SYMADDR(g_v, v);
    SYMADDR(g_scores, scores); SYMADDR(g_attn, attn); SYMADDR(g_aproj, aproj);
    SYMADDR(g_x, x); SYMADDR(g_h2, h2); SYMADDR(g_mid1, mid1); SYMADDR(g_mid2, mid2);
    SYMADDR(g_moe, moe); SYMADDR(g_topi, topi); SYMADDR(g_topw, topw);
    SYMADDR(g_tok, tok); SYMADDR(g_etw, etw); SYMADDR(g_cnt, cnt);

    // 1) pre-attn rmsnorm
    rmsnorm_kernel<<<CT, 256>>>(hidden, pre_attn, nullptr, hnorm);

    // 2) QKV projections
    sgemm_kernel<false, false><<<dim3(CNH * CDH / 128, CT / 128), 256>>>(
        hnorm, q_w, q, CT, CNH * CDH, CH, nullptr, nullptr, nullptr);
    sgemm_kernel<false, false><<<dim3(CNKV * CDH / 128, CT / 128), 256>>>(
        hnorm, k_w, k, CT, CNKV * CDH, CH, nullptr, nullptr, nullptr);
    sgemm_kernel<false, false><<<dim3(CNKV * CDH / 128, CT / 128), 256>>>(
        hnorm, v_w, v, CT, CNKV * CDH, CH, nullptr, nullptr, nullptr);

    // 3) RoPE
    rope_kernel<<<(CT * 20 * 32) / 256, 256>>>(q, k, posids);

    // 4) attention: scores (causal tiles) -> softmax -> PV
    attn_score_kernel<<<dim3(CS / 64, CS / 64, CB * CNH), 256>>>(q, k, scores);
    attn_softmax_kernel<<<dim3(CS, CB * CNH), 256>>>(scores, amask);
    attn_pv_kernel<<<dim3(CS / 64, CB * CNH), 256>>>(scores, v, attn);

    // 5) output projection + post-attn rmsnorm + residual
    sgemm_kernel<false, false><<<dim3(CH / 128, CT / 128), 256>>>(
        attn, o_w, aproj, CT, CH, CH, nullptr, nullptr, nullptr);
    rmsnorm_kernel<<<CT, 256>>>(aproj, post_attn, hidden, x);

    // 6) pre-moe rmsnorm
    rmsnorm_kernel<<<CT, 256>>>(x, pre_moe, nullptr, h2);

    // 7) gating + routing
    gate_kernel<<<CT, 128>>>(h2, gate_w, topi, topw);
    route_kernel<<<CE, 32>>>(topi, topw, tok, etw, cnt);

    // 8) sparse MoE (top-2): zero accumulator, then per-expert gather-GEMM / GEGLU / scatter-GEMM
    zero_kernel<<<(CT * CH) / 256, 256>>>(moe);
    for (int e = 0; e < CE; e++) {
        const float* wi = w_in  + (long)e * CH * CI;
        const float* wv = w_v   + (long)e * CH * CI;
        const float* wo = w_out + (long)e * CI * CH;
        sgemm_kernel<true, false><<<dim3(CI / 128, CT / 128), 256>>>(
            h2, wi, mid1, CT, CI, CH, tok + e * CT, nullptr, cnt + e);
        sgemm_kernel<true, false><<<dim3(CI / 128, CT / 128), 256>>>(
            h2, wv, mid2, CT, CI, CH, tok + e * CT, nullptr, cnt + e);
        glu_kernel<<<dim3(CI / 256, CT), 256>>>(mid1, mid2, cnt + e);
        sgemm_kernel<false, true><<<dim3(CH / 128, CT / 128), 256>>>(
            mid1, wo, moe, CT, CH, CI, tok + e * CT, etw + e * CT, cnt + e);
    }

    // 9) post-moe rmsnorm + residual -> output
    rmsnorm_kernel<<<CT, 256>>>(moe, post_moe, x, out);
}

// round 5
// speedup vs baseline: 3.4764x; 3.4764x over previous
#include <cuda_runtime.h>
#include <cuda_bf16.h>
#include <math.h>

// ---------------- problem constants ----------------
constexpr int CB   = 2;
constexpr int CS   = 1024;
constexpr int CH   = 1024;
constexpr int CNH  = 16;
constexpr int CNKV = 4;
constexpr int CDH  = 64;
constexpr int CI   = 4096;
constexpr int CE   = 8;
constexpr int CT   = CB * CS;          // 2048 tokens
constexpr int CSLOTS = 2 * CT;         // total (token, expert) slots
constexpr float CEPS = 1e-5f;

// ---------------- device scratch ----------------
__device__ float g_hnorm[CT * CH];
__device__ float g_q[CT * CNH * CDH];
__device__ float g_k[CT * CNKV * CDH];
__device__ float g_v[CT * CNKV * CDH];
__device__ float g_scores[(long)CB * CNH * CS * CS];   // 134 MB
__device__ float g_attn[CT * CH];
__device__ float g_aproj[CT * CH];
__device__ float g_x[CT * CH];
__device__ float g_h2[CT * CH];
__device__ int   g_topi[CT * 2];
__device__ float g_topw[CT * 2];
__device__ int   g_tok[CE * CT];
__device__ float g_etw[CE * CT];
__device__ int   g_cnt[CE];
__device__ int   g_off[CE + 1];
__device__ float g_mid1[(long)CSLOTS * CI];   // 64 MB
__device__ float g_mid2[(long)CSLOTS * CI];   // 64 MB
__device__ float g_moe[CT * CH];

// ---------------- rmsnorm (optionally + residual) ----------------
__global__ __launch_bounds__(256) void rmsnorm_kernel(
    const float* __restrict__ in, const float* __restrict__ sc,
    const float* __restrict__ resid, float* __restrict__ out)
{
    long row = blockIdx.x;
    const float* x = in + row * CH;
    int tid = threadIdx.x;
    float v[4];
    float ss = 0.f;
#pragma unroll
    for (int u = 0; u < 4; u++) {
        v[u] = x[tid + u * 256];
        ss += v[u] * v[u];
    }
    __shared__ float red[256];
    red[tid] = ss;
    __syncthreads();
    for (int s = 128; s > 0; s >>= 1) {
        if (tid < s) red[tid] += red[tid + s];
        __syncthreads();
    }
    float r = rsqrtf(red[0] * (1.0f / CH) + CEPS);
#pragma unroll
    for (int u = 0; u < 4; u++) {
        int h = tid + u * 256;
        float o = v[u] * r * sc[h];
        if (resid) o += resid[row * CH + h];
        out[row * CH + h] = o;
    }
}

// ============ core: 128x128x8 double-buffered SGEMM block ============
// 256 threads, 8x8 per thread in split 4+4 quads (tc, tc+64 / tr, tr+64).
// GATHER: A row m taken from row_idx[m]. SCATTER: C row m atomically added
// to row row_idx[m] scaled by row_w[m].
template <bool GATHER, bool SCATTER>
__device__ __forceinline__ void sgemm_block(
    const float* __restrict__ A, int lda,
    const float* __restrict__ B, int ldb,
    float* __restrict__ C, int ldc,
    int M, int K,
    int row_base, int col_base,
    const int* __restrict__ row_idx, const float* __restrict__ row_w)
{
    __shared__ float As[2][8][128];
    __shared__ float Bs[2][8][128];

    int tid = threadIdx.x;
    int arow = tid >> 1;               // 0..127
    int acol = (tid & 1) * 4;          // 0 or 4
    int brow = tid >> 5;               // 0..7
    int bcol = (tid & 31) * 4;         // 0..124

    int grow = row_base + arow;
    bool aval = grow < M;
    const float* aptr = A;             // dummy
    if (aval) {
        int r = GATHER ? row_idx[grow] : grow;
        aptr = A + (long)r * lda + acol;
    }
    const float* bptr = B + (long)brow * ldb + col_base + bcol;

    int tr = (tid >> 4) * 4;           // 0..60
    int tc = (tid & 15) * 4;           // 0..60

    float acc[8][8];
#pragma unroll
    for (int i = 0; i < 8; i++)
#pragma unroll
        for (int j = 0; j < 8; j++) acc[i][j] = 0.f;

    // prefetch k-tile 0
    float4 av = make_float4(0.f, 0.f, 0.f, 0.f);
    if (aval) av = *(const float4*)(aptr);
    float4 bv = *(const float4*)(bptr);
    As[0][acol + 0][arow] = av.x;
    As[0][acol + 1][arow] = av.y;
    As[0][acol + 2][arow] = av.z;
    As[0][acol + 3][arow] = av.w;
    *(float4*)&Bs[0][brow][bcol] = bv;
    __syncthreads();

    int buf = 0;
    int kiter = K >> 3;
    for (int it = 1; it <= kiter; ++it) {
        bool more = it < kiter;
        if (more) {
            int k0 = it << 3;
            av = make_float4(0.f, 0.f, 0.f, 0.f);
            if (aval) av = *(const float4*)(aptr + k0);
            bv = *(const float4*)(bptr + (long)k0 * ldb);
        }
        const float (*Ac)[128] = As[buf];
        const float (*Bc)[128] = Bs[buf];
#pragma unroll
        for (int kk = 0; kk < 8; kk++) {
            float4 a0 = *(const float4*)&Ac[kk][tr];
            float4 a1 = *(const float4*)&Ac[kk][tr + 64];
            float4 b0 = *(const float4*)&Bc[kk][tc];
            float4 b1 = *(const float4*)&Bc[kk][tc + 64];
            float af[8] = {a0.x, a0.y, a0.z, a0.w, a1.x, a1.y, a1.z, a1.w};
            float bf[8] = {b0.x, b0.y, b0.z, b0.w, b1.x, b1.y, b1.z, b1.w};
#pragma unroll
            for (int i = 0; i < 8; i++)
#pragma unroll
                for (int j = 0; j < 8; j++) acc[i][j] += af[i] * bf[j];
        }
        if (more) {
            int nb = buf ^ 1;
            As[nb][acol + 0][arow] = av.x;
            As[nb][acol + 1][arow] = av.y;
            As[nb][acol + 2][arow] = av.z;
            As[nb][acol + 3][arow] = av.w;
            *(float4*)&Bs[nb][brow][bcol] = bv;
            __syncthreads();
        }
        buf ^= 1;
    }

#pragma unroll
    for (int ii = 0; ii < 8; ii++) {
        int rofs = tr + ((ii < 4) ? ii : (60 + ii));
        int m = row_base + rofs;
        if (m >= M) continue;
        if (!SCATTER) {
            float* crow = C + (long)m * ldc + col_base;
            float4 c0 = make_float4(acc[ii][0], acc[ii][1], acc[ii][2], acc[ii][3]);
            float4 c1 = make_float4(acc[ii][4], acc[ii][5], acc[ii][6], acc[ii][7]);
            *(float4*)(crow + tc) = c0;
            *(float4*)(crow + tc + 64) = c1;
        } else {
            int tk = row_idx[m];
            float w = row_w[m];
            float* crow = C + (long)tk * ldc + col_base;
#pragma unroll
            for (int j = 0; j < 4; j++) atomicAdd(crow + tc + j, w * acc[ii][j]);
#pragma unroll
            for (int j = 0; j < 4; j++) atomicAdd(crow + tc + 64 + j, w * acc[ii][4 + j]);
        }
    }
}

// ---------------- fused QKV projection (one launch) ----------------
__global__ __launch_bounds__(256) void qkv_kernel(
    const float* __restrict__ hnorm,
    const float* __restrict__ qw, const float* __restrict__ kw, const float* __restrict__ vw,
    float* __restrict__ q, float* __restrict__ k, float* __restrict__ v)
{
    int x = blockIdx.x;   // 0..11
    const float* B; float* C; int ld; int col;
    if (x < 8)       { B = qw; C = q; ld = CNH * CDH;  col = x * 128; }
    else if (x < 10) { B = kw; C = k; ld = CNKV * CDH; col = (x - 8) * 128; }
    else             { B = vw; C = v; ld = CNKV * CDH; col = (x - 10) * 128; }
    sgemm_block<false, false>(hnorm, CH, B, ld, C, ld, CT, CH,
                              blockIdx.y * 128, col, nullptr, nullptr);
}

// ---------------- plain GEMM (O projection) ----------------
__global__ __launch_bounds__(256) void gemm_plain_kernel(
    const float* __restrict__ A, const float* __restrict__ B, float* __restrict__ C,
    int M, int N, int K)
{
    sgemm_block<false, false>(A, K, B, N, C, N, M, K,
                              blockIdx.y * 128, blockIdx.x * 128, nullptr, nullptr);
}

// ---------------- MoE stage 1: gather-GEMM, all experts + both matrices, one launch ----------------
__global__ __launch_bounds__(256) void moe_stage1_kernel(
    const float* __restrict__ h2,
    const float* __restrict__ w_in, const float* __restrict__ w_v,
    float* __restrict__ mid1, float* __restrict__ mid2,
    const int* __restrict__ tok, const int* __restrict__ cnt, const int* __restrict__ off)
{
    int z = blockIdx.z;
    int e = z >> 1;
    int which = z & 1;
    int M = cnt[e];
    int row_base = blockIdx.y * 128;
    if (row_base >= M) return;
    const float* B = (which ? w_v : w_in) + (long)e * CH * CI;
    float* C = (which ? mid2 : mid1) + (long)off[e] * CI;
    sgemm_block<true, false>(h2, CH, B, CI, C, CI, M, CH,
                             row_base, blockIdx.x * 128, tok + e * CT, nullptr);
}

// ---------------- MoE stage 2: weighted scatter-GEMM, all experts, one launch ----------------
__global__ __launch_bounds__(256) void moe_stage2_kernel(
    const float* __restrict__ mid1, const float* __restrict__ w_out, float* __restrict__ moe,
    const int* __restrict__ tok, const float* __restrict__ etw,
    const int* __restrict__ cnt, const int* __restrict__ off)
{
    int e = blockIdx.z;
    int M = cnt[e];
    int row_base = blockIdx.y * 128;
    if (row_base >= M) return;
    const float* A = mid1 + (long)off[e] * CI;
    const float* B = w_out + (long)e * CI * CH;
    sgemm_block<false, true>(A, CI, B, CH, moe, CH, M, CI,
                             row_base, blockIdx.x * 128, tok + e * CT, etw + e * CT);
}

// ---------------- RoPE on q (16 heads) and k (4 heads) ----------------
__global__ __launch_bounds__(256) void rope_kernel(
    float* __restrict__ q, float* __restrict__ k, const int* __restrict__ pos)
{
    long idx = (long)blockIdx.x * 256 + threadIdx.x;   // token*20heads*32
    if (idx >= (long)CT * 20 * 32) return;
    int d = idx & 31;
    int hh = (int)((idx >> 5) % 20);
    int t = (int)(idx / (32 * 20));
    float p = (float)pos[t];
    float inv = powf(10000.0f, -((float)d) / 32.0f);
    float ang = p * inv;
    float c = cosf(ang), s = sinf(ang);
    float* ptr;
    if (hh < CNH) ptr = q + (long)t * (CNH * CDH) + hh * CDH;
    else          ptr = k + (long)t * (CNKV * CDH) + (hh - CNH) * CDH;
    float x1 = ptr[d], x2 = ptr[d + 32];
    ptr[d]      = x1 * c - x2 * s;
    ptr[d + 32] = x2 * c + x1 * s;
}

// ---------------- attention scores: one 64x64 tile per block, causal tiles only ----------------
__global__ __launch_bounds__(256) void attn_score_kernel(
    const float* __restrict__ q, const float* __restrict__ k, float* __restrict__ scores)
{
    int jt = blockIdx.x, it = blockIdx.y;
    if (jt > it) return;
    int bh = blockIdx.z;
    int b = bh >> 4, h = bh & 15, kv = h >> 2;

    __shared__ float Qs[64][68];   // [d][i]
    __shared__ float Ks[64][68];   // [d][j]
    int tid = threadIdx.x;
#pragma unroll
    for (int l = 0; l < 4; l++) {
        int e = tid + l * 256;
        int r = e >> 4;
        int c = (e & 15) << 2;
        float4 a = *(const float4*)(q + (long)(b * CS + it * 64 + r) * (CNH * CDH) + h * CDH + c);
        Qs[c][r] = a.x; Qs[c + 1][r] = a.y; Qs[c + 2][r] = a.z; Qs[c + 3][r] = a.w;
        float4 bb = *(const float4*)(k + (long)(b * CS + jt * 64 + r) * (CNKV * CDH) + kv * CDH + c);
        Ks[c][r] = bb.x; Ks[c + 1][r] = bb.y; Ks[c + 2][r] = bb.z; Ks[c + 3][r] = bb.w;
    }
    __syncthreads();

    int ti = (tid >> 4) << 2;
    int tj = (tid & 15) << 2;
    float acc[4][4] = {};
#pragma unroll 8
    for (int d = 0; d < 64; d++) {
        float4 a = *(const float4*)&Qs[d][ti];
        float4 bb = *(const float4*)&Ks[d][tj];
        float af[4] = {a.x, a.y, a.z, a.w};
        float bf[4] = {bb.x, bb.y, bb.z, bb.w};
#pragma unroll
        for (int i = 0; i < 4; i++)
#pragma unroll
            for (int j = 0; j < 4; j++) acc[i][j] += af[i] * bf[j];
    }
    const float scale = 0.125f;  // DH^-0.5
#pragma unroll
    for (int i = 0; i < 4; i++) {
        long rbase = ((long)bh * CS + it * 64 + ti + i) * CS + jt * 64 + tj;
#pragma unroll
        for (int j = 0; j < 4; j++) scores[rbase + j] = acc[i][j] * scale;
    }
}

// ---------------- causal masked softmax, in-place; zero-pads tail of diag tile ----------------
__global__ __launch_bounds__(256) void attn_softmax_kernel(
    float* __restrict__ scores, const int* __restrict__ amask)
{
    int i = blockIdx.x, bh = blockIdx.y;
    int b = bh >> 4;
    float* row = scores + ((long)bh * CS + i) * CS;
    int len = i + 1;
    int jceil = ((i >> 6) + 1) << 6;
    int tid = threadIdx.x;
    __shared__ float red[256];

    float mx = -1e30f;
    for (int j = tid; j < len; j += 256) {
        float v = (amask[b * CS + j] > 0) ? row[j] : -1e9f;
        mx = fmaxf(mx, v);
    }
    red[tid] = mx; __syncthreads();
    for (int s = 128; s > 0; s >>= 1) {
        if (tid < s) red[tid] = fmaxf(red[tid], red[tid + s]);
        __syncthreads();
    }
    float M = red[0]; __syncthreads();

    float sum = 0.f;
    for (int j = tid; j < len; j += 256) {
        float v = (amask[b * CS + j] > 0) ? row[j] : -1e9f;
        sum += expf(v - M);
    }
    red[tid] = sum; __syncthreads();
    for (int s = 128; s > 0; s >>= 1) {
        if (tid < s) red[tid] += red[tid + s];
        __syncthreads();
    }
    float inv = 1.0f / red[0];

    for (int j = tid; j < len; j += 256) {
        float v = (amask[b * CS + j] > 0) ? row[j] : -1e9f;
        row[j] = expf(v - M) * inv;
    }
    for (int j = len + tid; j < jceil; j += 256) row[j] = 0.f;
}

// ---------------- PV: out[64 x 64] per (it, bh), looping causal j-tiles ----------------
__global__ __launch_bounds__(256) void attn_pv_kernel(
    const float* __restrict__ probs, const float* __restrict__ v, float* __restrict__ attn)
{
    int it = blockIdx.x;
    int bh = blockIdx.y;
    int b = bh >> 4, h = bh & 15, kv = h >> 2;

    __shared__ float Ps[64][68];  // [j][i]
    __shared__ float Vs[64][68];  // [j][d]
    int tid = threadIdx.x;
    int ti = (tid >> 4) << 2;
    int td = (tid & 15) << 2;
    float acc[4][4] = {};

    for (int jt = 0; jt <= it; jt++) {
#pragma unroll
        for (int l = 0; l < 4; l++) {
            int e = tid + l * 256;
            int r = e >> 4;
            int c = (e & 15) << 2;
            float4 p = *(const float4*)(probs + ((long)bh * CS + it * 64 + r) * CS + jt * 64 + c);
            Ps[c][r] = p.x; Ps[c + 1][r] = p.y; Ps[c + 2][r] = p.z; Ps[c + 3][r] = p.w;
            float4 vv = *(const float4*)(v + (long)(b * CS + jt * 64 + r) * (CNKV * CDH) + kv * CDH + c);
            *(float4*)&Vs[r][c] = vv;
        }
        __syncthreads();
#pragma unroll 8
        for (int jj = 0; jj < 64; jj++) {
            float4 a = *(const float4*)&Ps[jj][ti];
            float4 bb = *(const float4*)&Vs[jj][td];
            float af[4] = {a.x, a.y, a.z, a.w};
            float bf[4] = {bb.x, bb.y, bb.z, bb.w};
#pragma unroll
            for (int i = 0; i < 4; i++)
#pragma unroll
                for (int j = 0; j < 4; j++) acc[i][j] += af[i] * bf[j];
        }
        __syncthreads();
    }
#pragma unroll
    for (int i = 0; i < 4; i++) {
        long rbase = (long)(b * CS + it * 64 + ti + i) * CH + h * CDH + td;
#pragma unroll
        for (int j = 0; j < 4; j++) attn[rbase + j] = acc[i][j];
    }
}

// ---------------- MoE gating: softmax over 8 logits + top-2 ----------------
__global__ __launch_bounds__(128) void gate_kernel(
    const float* __restrict__ h2, const float* __restrict__ gw,
    int* __restrict__ topi, float* __restrict__ topw)
{
    int t = blockIdx.x;
    int tid = threadIdx.x;
    float p[8] = {};
    for (int hh = tid; hh < CH; hh += 128) {
        float x = h2[(long)t * CH + hh];
        const float* g = gw + hh * CE;
#pragma unroll
        for (int e = 0; e < 8; e++) p[e] += x * g[e];
    }
    __shared__ float red[128 * 8];
#pragma unroll
    for (int e = 0; e < 8; e++) red[tid * 8 + e] = p[e];
    __syncthreads();
    for (int s = 64; s > 0; s >>= 1) {
        if (tid < s)
#pragma unroll
            for (int e = 0; e < 8; e++) red[tid * 8 + e] += red[(tid + s) * 8 + e];
        __syncthreads();
    }
    if (tid == 0) {
        float lg[8], pr[8];
        float m = -1e30f;
#pragma unroll
        for (int e = 0; e < 8; e++) { lg[e] = red[e]; m = fmaxf(m, lg[e]); }
        float sum = 0.f;
#pragma unroll
        for (int e = 0; e < 8; e++) { pr[e] = expf(lg[e] - m); sum += pr[e]; }
        float inv = 1.0f / sum;
#pragma unroll
        for (int e = 0; e < 8; e++) pr[e] *= inv;
        int i0 = 0;
#pragma unroll
        for (int e = 1; e < 8; e++) if (pr[e] > pr[i0]) i0 = e;
        int i1 = -1;
#pragma unroll
        for (int e = 0; e < 8; e++) {
            if (e == i0) continue;
            if (i1 < 0 || pr[e] > pr[i1]) i1 = e;
        }
        topi[t * 2] = i0; topi[t * 2 + 1] = i1;
        topw[t * 2] = pr[i0]; topw[t * 2 + 1] = pr[i1];
    }
}

// ---------------- per-expert token compaction + prefix offsets (one block) ----------------
__global__ __launch_bounds__(256) void route_kernel(
    const int* __restrict__ topi, const float* __restrict__ topw,
    int* __restrict__ tok, float* __restrict__ etw,
    int* __restrict__ cnt, int* __restrict__ off)
{
    int e = threadIdx.x >> 5;      // warp = expert
    int lane = threadIdx.x & 31;
    int count = 0;
    for (int base = 0; base < CT; base += 32) {
        int t = base + lane;
        int i0 = topi[t * 2], i1 = topi[t * 2 + 1];
        bool sel = (i0 == e) || (i1 == e);
        float w = (i0 == e) ? topw[t * 2] : topw[t * 2 + 1];
        unsigned m = __ballot_sync(0xFFFFFFFFu, sel);
        int pos = count + __popc(m & ((1u << lane) - 1u));
        if (sel) {
            tok[e * CT + pos] = t;
            etw[e * CT + pos] = w;
        }
        count += __popc(m);
    }
    if (lane == 0) cnt[e] = count;
    __syncthreads();
    if (threadIdx.x == 0) {
        int s = 0;
        for (int i = 0; i < CE; i++) { off[i] = s; s += cnt[i]; }
        off[CE] = s;
    }
}

// ---------------- GEGLU over compacted slots: mid1 = gelu_tanh(mid1) * mid2 ----------------
__global__ __launch_bounds__(256) void glu_kernel(
    float* __restrict__ a, const float* __restrict__ b, const int* __restrict__ off)
{
    int row = blockIdx.y;
    if (row >= off[CE]) return;
    long idx = (long)row * CI + blockIdx.x * 256 + threadIdx.x;
    float x = a[idx];
    float g = 0.5f * x * (1.0f + tanhf(0.7978845608028654f * (x + 0.044715f * x * x * x)));
    a[idx] = g * b[idx];
}

// ---------------- zero fill ----------------
__global__ __launch_bounds__(256) void zero_kernel(float* __restrict__ p)
{
    p[(long)blockIdx.x * 256 + threadIdx.x] = 0.f;
}

// ---------------- host orchestration ----------------
#define SYMADDR(var, ptr) do { void* _p = nullptr; cudaGetSymbolAddress(&_p, var); ptr = (decltype(ptr))_p; } while (0)

extern "C" void kernel_launch(void* const* d_in, const int* in_sizes, int n_in,
                              void* d_out, int out_size)
{
    const float* hidden   = (const float*)d_in[0];
    const int*   amask    = (const int*)d_in[1];
    const int*   posids   = (const int*)d_in[2];
    const float* q_w      = (const float*)d_in[3];
    const float* k_w      = (const float*)d_in[4];
    const float* v_w      = (const float*)d_in[5];
    const float* o_w      = (const float*)d_in[6];
    const float* pre_attn = (const float*)d_in[7];
    const float* post_attn= (const float*)d_in[8];
    const float* pre_moe  = (const float*)d_in[9];
    const float* post_moe = (const float*)d_in[10];
    const float* gate_w   = (const float*)d_in[11];
    const float* w_in     = (const float*)d_in[12];
    const float* w_v      = (const float*)d_in[13];
    const float* w_out    = (const float*)d_in[14];
    float* out = (float*)d_out;

    float *hnorm, *q, *k, *v, *scores, *attn, *aproj, *x, *h2, *mid1, *mid2, *moe, *topw, *etw;
    int *topi, *tok, *cnt, *off;
    SYMADDR(g_hnorm, hnorm); SYMADDR(g_q, q); SYMADDR(g_k, k); SYMADDR(g_v, v);
    SYMADDR(g_scores, scores); SYMADDR(g_attn, attn); SYMADDR(g_aproj, aproj);
    SYMADDR(g_x, x); SYMADDR(g_h2, h2); SYMADDR(g_mid1, mid1); SYMADDR(g_mid2, mid2);
    SYMADDR(g_moe, moe); SYMADDR(g_topi, topi); SYMADDR(g_topw, topw);
    SYMADDR(g_tok, tok); SYMADDR(g_etw, etw); SYMADDR(g_cnt, cnt); SYMADDR(g_off, off);

    // 1) pre-attn rmsnorm
    rmsnorm_kernel<<<CT, 256>>>(hidden, pre_attn, nullptr, hnorm);

    // 2) fused QKV projections (one launch, 192 blocks)
    qkv_kernel<<<dim3(12, CT / 128), 256>>>(hnorm, q_w, k_w, v_w, q, k, v);

    // 3) RoPE
    rope_kernel<<<(CT * 20 * 32) / 256, 256>>>(q, k, posids);

    // 4) attention: scores (causal tiles) -> softmax -> PV
    attn_score_kernel<<<dim3(CS / 64, CS / 64, CB * CNH), 256>>>(q, k, scores);
    attn_softmax_kernel<<<dim3(CS, CB * CNH), 256>>>(scores, amask);
    attn_pv_kernel<<<dim3(CS / 64, CB * CNH), 256>>>(scores, v, attn);

    // 5) output projection + post-attn rmsnorm + residual
    gemm_plain_kernel<<<dim3(CH / 128, CT / 128), 256>>>(attn, o_w, aproj, CT, CH, CH);
    rmsnorm_kernel<<<CT, 256>>>(aproj, post_attn, hidden, x);

    // 6) pre-moe rmsnorm
    rmsnorm_kernel<<<CT, 256>>>(x, pre_moe, nullptr, h2);

    // 7) gating + routing (compaction + prefix offsets)
    gate_kernel<<<CT, 128>>>(h2, gate_w, topi, topw);
    route_kernel<<<1, 256>>>(topi, topw, tok, etw, cnt, off);

    // 8) sparse MoE: all experts concurrent
    zero_kernel<<<(CT * CH) / 256, 256>>>(moe);
    moe_stage1_kernel<<<dim3(CI / 128, CT / 128, CE * 2), 256>>>(
        h2, w_in, w_v, mid1, mid2, tok, cnt, off);
    glu_kernel<<<dim3(CI / 256, CSLOTS), 256>>>(mid1, mid2, off);
    moe_stage2_kernel<<<dim3(CH / 128, CT / 128, CE), 256>>>(
        mid1, w_out, moe, tok, etw, cnt, off);

    // 9) post-moe rmsnorm + residual -> output
    rmsnorm_kernel<<<CT, 256>>>(moe, post_moe, x, out);
}

// round 9
// speedup vs baseline: 5.3320x; 1.5338x over previous
#include <cuda_runtime.h>
#include <math.h>
#include <stdint.h>

// ---------------- problem constants ----------------
constexpr int CB   = 2;
constexpr int CS   = 1024;
constexpr int CH   = 1024;
constexpr int CNH  = 16;
constexpr int CNKV = 4;
constexpr int CDH  = 64;
constexpr int CI   = 4096;
constexpr int CE   = 8;
constexpr int CT   = CB * CS;          // 2048 tokens
constexpr int CSLOTS = 2 * CT;         // total (token, expert) slots
constexpr float CEPS = 1e-5f;

// ---------------- device scratch ----------------
__device__ float g_hnorm[CT * CH];
__device__ float g_q[CT * CNH * CDH];
__device__ float g_k[CT * CNKV * CDH];
__device__ float g_v[CT * CNKV * CDH];
__device__ float g_scores[(long)CB * CNH * CS * CS];   // 134 MB
__device__ float g_attn[CT * CH];
__device__ float g_aproj[CT * CH];
__device__ float g_x[CT * CH];
__device__ float g_h2[CT * CH];
__device__ int   g_topi[CT * 2];
__device__ float g_topw[CT * 2];
__device__ int   g_tok[CE * CT];
__device__ float g_etw[CE * CT];
__device__ int   g_cnt[CE];
__device__ int   g_off[CE + 1];
__device__ float g_mid1[(long)CSLOTS * CI];   // 64 MB
__device__ float g_mid2[(long)CSLOTS * CI];   // 64 MB
__device__ float g_moe[CT * CH];

// ---------------- rmsnorm (optionally + residual) ----------------
__global__ __launch_bounds__(256) void rmsnorm_kernel(
    const float* __restrict__ in, const float* __restrict__ sc,
    const float* __restrict__ resid, float* __restrict__ out)
{
    long row = blockIdx.x;
    const float* x = in + row * CH;
    int tid = threadIdx.x;
    float v[4];
    float ss = 0.f;
#pragma unroll
    for (int u = 0; u < 4; u++) {
        v[u] = x[tid + u * 256];
        ss += v[u] * v[u];
    }
    __shared__ float red[256];
    red[tid] = ss;
    __syncthreads();
    for (int s = 128; s > 0; s >>= 1) {
        if (tid < s) red[tid] += red[tid + s];
        __syncthreads();
    }
    float r = rsqrtf(red[0] * (1.0f / CH) + CEPS);
#pragma unroll
    for (int u = 0; u < 4; u++) {
        int h = tid + u * 256;
        float o = v[u] * r * sc[h];
        if (resid) o += resid[row * CH + h];
        out[row * CH + h] = o;
    }
}

// ================= bf16x3 split tensor-core GEMM core =================
// fp32 emulation: x = hi + lo (bf16 each, 16 effective mantissa bits);
// A*B ~= Ahi*Bhi + Alo*Bhi + Ahi*Blo  (3x mma.m16n8k16.bf16, fp32 accum).
// 128x128 block tile, 256 threads (8 warps), warp tile 32x64, K-tile 16,
// double-buffered SMEM (one sync per K-tile).
// GATHER: A row m taken from row_idx[m].
// SCATTER: C row m atomically added to row row_idx[m], scaled by row_w[m].

// round-to-nearest-even bf16, returned as fp32 bit pattern (low 16 bits zero).
// Pure integer ops; inputs here are finite (no NaN handling needed).
__device__ __forceinline__ uint32_t bf16_rne_bits(float x) {
    uint32_t u = __float_as_uint(x);
    uint32_t r = u + 0x7FFFu + ((u >> 16) & 1u);
    return r & 0xFFFF0000u;
}

// x0 -> low 16 bits (smaller k index), x1 -> high 16 bits
__device__ __forceinline__ void split_pack(float x0, float x1, uint32_t& hi, uint32_t& lo) {
    uint32_t h0b = bf16_rne_bits(x0);
    uint32_t h1b = bf16_rne_bits(x1);
    // residual is exact in fp32 (hi has >=8 fewer significand bits than x)
    float l0 = x0 - __uint_as_float(h0b);
    float l1 = x1 - __uint_as_float(h1b);
    uint32_t l0b = bf16_rne_bits(l0);
    uint32_t l1b = bf16_rne_bits(l1);
    hi = (h0b >> 16) | (h1b & 0xFFFF0000u);
    lo = (l0b >> 16) | (l1b & 0xFFFF0000u);
}

__device__ __forceinline__ void mma_bf16(float* c, const uint32_t* a, const uint32_t* b) {
    asm volatile(
        "mma.sync.aligned.m16n8k16.row.col.f32.bf16.bf16.f32 "
        "{%0,%1,%2,%3}, {%4,%5,%6,%7}, {%8,%9}, {%0,%1,%2,%3};"
        : "+f"(c[0]), "+f"(c[1]), "+f"(c[2]), "+f"(c[3])
        : "r"(a[0]), "r"(a[1]), "r"(a[2]), "r"(a[3]), "r"(b[0]), "r"(b[1]));
}

template <bool GATHER, bool SCATTER>
__device__ __forceinline__ void mma_gemm_block(
    const float* __restrict__ A, int lda,
    const float* __restrict__ B, int ldb,
    float* __restrict__ C, int ldc,
    int M, int K,
    int row_base, int col_base,
    const int* __restrict__ row_idx, const float* __restrict__ row_w)
{
    // packed bf16x2 k-pairs; strides chosen for conflict-free fragment loads
    __shared__ uint32_t Ahi[2][128][12], Alo[2][128][12];   // [m][k/2], stride 12
    __shared__ uint32_t Bhi[2][8][136],  Blo[2][8][136];    // [k/2][n], stride 136

    int tid  = threadIdx.x;
    int lane = tid & 31;
    int warp = tid >> 5;
    int g  = lane >> 2;   // 0..7
    int t4 = lane & 3;    // 0..3
    int m_warp = (warp & 3) * 32;
    int n_warp = (warp >> 2) * 64;

    // A global loader: thread -> row m_l, k = kq..kq+7 (2 float4)
    int m_l = tid >> 1;
    int kq  = (tid & 1) * 8;
    int kq2 = (tid & 1) * 4;
    int ar  = row_base + m_l;
    bool aval = ar < M;
    const float* aptr = A;
    if (aval) {
        int r = GATHER ? row_idx[ar] : ar;
        aptr = A + (long)r * lda + kq;
    }
    // B global loader: thread -> k-pair row 2*k2_l(+1), cols n_l..n_l+3
    int k2_l = tid >> 5;          // 0..7
    int n_l  = (tid & 31) * 4;    // 0..124
    const float* bptr = B + (long)(2 * k2_l) * ldb + col_base + n_l;

    float acc[2][8][4];
#pragma unroll
    for (int i = 0; i < 2; i++)
#pragma unroll
        for (int j = 0; j < 8; j++)
#pragma unroll
            for (int l = 0; l < 4; l++) acc[i][j][l] = 0.f;

    float4 pa0, pa1, pb0, pb1;

    // ---- prologue: global load tile 0, split+store ----
    pa0 = make_float4(0.f, 0.f, 0.f, 0.f); pa1 = pa0;
    if (aval) { pa0 = *(const float4*)(aptr); pa1 = *(const float4*)(aptr + 4); }
    pb0 = *(const float4*)(bptr);
    pb1 = *(const float4*)(bptr + ldb);
    {
        uint32_t h, l;
        split_pack(pa0.x, pa0.y, h, l); Ahi[0][m_l][kq2 + 0] = h; Alo[0][m_l][kq2 + 0] = l;
        split_pack(pa0.z, pa0.w, h, l); Ahi[0][m_l][kq2 + 1] = h; Alo[0][m_l][kq2 + 1] = l;
        split_pack(pa1.x, pa1.y, h, l); Ahi[0][m_l][kq2 + 2] = h; Alo[0][m_l][kq2 + 2] = l;
        split_pack(pa1.z, pa1.w, h, l); Ahi[0][m_l][kq2 + 3] = h; Alo[0][m_l][kq2 + 3] = l;
        split_pack(pb0.x, pb1.x, h, l); Bhi[0][k2_l][n_l + 0] = h; Blo[0][k2_l][n_l + 0] = l;
        split_pack(pb0.y, pb1.y, h, l); Bhi[0][k2_l][n_l + 1] = h; Blo[0][k2_l][n_l + 1] = l;
        split_pack(pb0.z, pb1.z, h, l); Bhi[0][k2_l][n_l + 2] = h; Blo[0][k2_l][n_l + 2] = l;
        split_pack(pb0.w, pb1.w, h, l); Bhi[0][k2_l][n_l + 3] = h; Blo[0][k2_l][n_l + 3] = l;
    }
    __syncthreads();

    int KT = K >> 4;
    for (int kt = 0; kt < KT; kt++) {
        // prefetch next K-tile into registers (overlaps mma below)
        if (kt + 1 < KT) {
            long ko = (long)(kt + 1) * 16;
            pa0 = make_float4(0.f, 0.f, 0.f, 0.f); pa1 = pa0;
            if (aval) { pa0 = *(const float4*)(aptr + ko); pa1 = *(const float4*)(aptr + ko + 4); }
            const float* bp = bptr + ko * ldb;
            pb0 = *(const float4*)(bp);
            pb1 = *(const float4*)(bp + ldb);
        }

        int buf = kt & 1;
        // fragment loads (same index scheme as verified tf32 layout, k packed in pairs)
        uint32_t ah[2][4], al[2][4];
#pragma unroll
        for (int mf = 0; mf < 2; mf++) {
            int mb = m_warp + mf * 16 + g;
            ah[mf][0] = Ahi[buf][mb][t4];         al[mf][0] = Alo[buf][mb][t4];
            ah[mf][1] = Ahi[buf][mb + 8][t4];     al[mf][1] = Alo[buf][mb + 8][t4];
            ah[mf][2] = Ahi[buf][mb][t4 + 4];     al[mf][2] = Alo[buf][mb][t4 + 4];
            ah[mf][3] = Ahi[buf][mb + 8][t4 + 4]; al[mf][3] = Alo[buf][mb + 8][t4 + 4];
        }
        uint32_t bh[8][2], bl[8][2];
#pragma unroll
        for (int nf = 0; nf < 8; nf++) {
            int nb = n_warp + nf * 8 + g;
            bh[nf][0] = Bhi[buf][t4][nb];     bl[nf][0] = Blo[buf][t4][nb];
            bh[nf][1] = Bhi[buf][t4 + 4][nb]; bl[nf][1] = Blo[buf][t4 + 4][nb];
        }
#pragma unroll
        for (int mf = 0; mf < 2; mf++)
#pragma unroll
            for (int nf = 0; nf < 8; nf++) {
                mma_bf16(acc[mf][nf], ah[mf], bh[nf]);
                mma_bf16(acc[mf][nf], al[mf], bh[nf]);
                mma_bf16(acc[mf][nf], ah[mf], bl[nf]);
            }

        if (kt + 1 < KT) {
            int nb = (kt + 1) & 1;
            uint32_t h, l;
            split_pack(pa0.x, pa0.y, h, l); Ahi[nb][m_l][kq2 + 0] = h; Alo[nb][m_l][kq2 + 0] = l;
            split_pack(pa0.z, pa0.w, h, l); Ahi[nb][m_l][kq2 + 1] = h; Alo[nb][m_l][kq2 + 1] = l;
            split_pack(pa1.x, pa1.y, h, l); Ahi[nb][m_l][kq2 + 2] = h; Alo[nb][m_l][kq2 + 2] = l;
            split_pack(pa1.z, pa1.w, h, l); Ahi[nb][m_l][kq2 + 3] = h; Alo[nb][m_l][kq2 + 3] = l;
            split_pack(pb0.x, pb1.x, h, l); Bhi[nb][k2_l][n_l + 0] = h; Blo[nb][k2_l][n_l + 0] = l;
            split_pack(pb0.y, pb1.y, h, l); Bhi[nb][k2_l][n_l + 1] = h; Blo[nb][k2_l][n_l + 1] = l;
            split_pack(pb0.z, pb1.z, h, l); Bhi[nb][k2_l][n_l + 2] = h; Blo[nb][k2_l][n_l + 2] = l;
            split_pack(pb0.w, pb1.w, h, l); Bhi[nb][k2_l][n_l + 3] = h; Blo[nb][k2_l][n_l + 3] = l;
            __syncthreads();
        }
    }

    // ---- epilogue (c-frag layout identical to m16n8k8) ----
#pragma unroll
    for (int mf = 0; mf < 2; mf++) {
        int r0 = row_base + m_warp + mf * 16 + g;
        int r1 = r0 + 8;
        bool v0 = r0 < M, v1 = r1 < M;
        if (!SCATTER) {
#pragma unroll
            for (int nf = 0; nf < 8; nf++) {
                int c = col_base + n_warp + nf * 8 + t4 * 2;
                if (v0) *(float2*)&C[(long)r0 * ldc + c] = make_float2(acc[mf][nf][0], acc[mf][nf][1]);
                if (v1) *(float2*)&C[(long)r1 * ldc + c] = make_float2(acc[mf][nf][2], acc[mf][nf][3]);
            }
        } else {
            int tk0 = 0, tk1 = 0; float w0 = 0.f, w1 = 0.f;
            if (v0) { tk0 = row_idx[r0]; w0 = row_w[r0]; }
            if (v1) { tk1 = row_idx[r1]; w1 = row_w[r1]; }
#pragma unroll
            for (int nf = 0; nf < 8; nf++) {
                int c = col_base + n_warp + nf * 8 + t4 * 2;
                if (v0) {
                    atomicAdd(&C[(long)tk0 * ldc + c],     w0 * acc[mf][nf][0]);
                    atomicAdd(&C[(long)tk0 * ldc + c + 1], w0 * acc[mf][nf][1]);
                }
                if (v1) {
                    atomicAdd(&C[(long)tk1 * ldc + c],     w1 * acc[mf][nf][2]);
                    atomicAdd(&C[(long)tk1 * ldc + c + 1], w1 * acc[mf][nf][3]);
                }
            }
        }
    }
}

// ---------------- fused QKV projection (one launch) ----------------
__global__ __launch_bounds__(256) void qkv_kernel(
    const float* __restrict__ hnorm,
    const float* __restrict__ qw, const float* __restrict__ kw, const float* __restrict__ vw,
    float* __restrict__ q, float* __restrict__ k, float* __restrict__ v)
{
    int x = blockIdx.x;   // 0..11
    const float* B; float* C; int ld; int col;
    if (x < 8)       { B = qw; C = q; ld = CNH * CDH;  col = x * 128; }
    else if (x < 10) { B = kw; C = k; ld = CNKV * CDH; col = (x - 8) * 128; }
    else             { B = vw; C = v; ld = CNKV * CDH; col = (x - 10) * 128; }
    mma_gemm_block<false, false>(hnorm, CH, B, ld, C, ld, CT, CH,
                                 blockIdx.y * 128, col, nullptr, nullptr);
}

// ---------------- plain GEMM (O projection) ----------------
__global__ __launch_bounds__(256) void gemm_plain_kernel(
    const float* __restrict__ A, const float* __restrict__ B, float* __restrict__ C,
    int M, int N, int K)
{
    mma_gemm_block<false, false>(A, K, B, N, C, N, M, K,
                                 blockIdx.y * 128, blockIdx.x * 128, nullptr, nullptr);
}

// ---------------- MoE stage 1: gather-GEMM, all experts + both matrices ----------------
__global__ __launch_bounds__(256) void moe_stage1_kernel(
    const float* __restrict__ h2,
    const float* __restrict__ w_in, const float* __restrict__ w_v,
    float* __restrict__ mid1, float* __restrict__ mid2,
    const int* __restrict__ tok, const int* __restrict__ cnt, const int* __restrict__ off)
{
    int z = blockIdx.z;
    int e = z >> 1;
    int which = z & 1;
    int M = cnt[e];
    int row_base = blockIdx.y * 128;
    if (row_base >= M) return;
    const float* B = (which ? w_v : w_in) + (long)e * CH * CI;
    float* C = (which ? mid2 : mid1) + (long)off[e] * CI;
    mma_gemm_block<true, false>(h2, CH, B, CI, C, CI, M, CH,
                                row_base, blockIdx.x * 128, tok + e * CT, nullptr);
}

// ---------------- MoE stage 2: weighted scatter-GEMM, all experts ----------------
__global__ __launch_bounds__(256) void moe_stage2_kernel(
    const float* __restrict__ mid1, const float* __restrict__ w_out, float* __restrict__ moe,
    const int* __restrict__ tok, const float* __restrict__ etw,
    const int* __restrict__ cnt, const int* __restrict__ off)
{
    int e = blockIdx.z;
    int M = cnt[e];
    int row_base = blockIdx.y * 128;
    if (row_base >= M) return;
    const float* A = mid1 + (long)off[e] * CI;
    const float* B = w_out + (long)e * CI * CH;
    mma_gemm_block<false, true>(A, CI, B, CH, moe, CH, M, CI,
                                row_base, blockIdx.x * 128, tok + e * CT, etw + e * CT);
}

// ---------------- RoPE on q (16 heads) and k (4 heads) ----------------
__global__ __launch_bounds__(256) void rope_kernel(
    float* __restrict__ q, float* __restrict__ k, const int* __restrict__ pos)
{
    long idx = (long)blockIdx.x * 256 + threadIdx.x;   // token*20heads*32
    if (idx >= (long)CT * 20 * 32) return;
    int d = idx & 31;
    int hh = (int)((idx >> 5) % 20);
    int t = (int)(idx / (32 * 20));
    float p = (float)pos[t];
    float inv = powf(10000.0f, -((float)d) / 32.0f);
    float ang = p * inv;
    float c = cosf(ang), s = sinf(ang);
    float* ptr;
    if (hh < CNH) ptr = q + (long)t * (CNH * CDH) + hh * CDH;
    else          ptr = k + (long)t * (CNKV * CDH) + (hh - CNH) * CDH;
    float x1 = ptr[d], x2 = ptr[d + 32];
    ptr[d]      = x1 * c - x2 * s;
    ptr[d + 32] = x2 * c + x1 * s;
}

// ---------------- attention scores: one 64x64 tile per block, causal tiles only ----------------
__global__ __launch_bounds__(256) void attn_score_kernel(
    const float* __restrict__ q, const float* __restrict__ k, float* __restrict__ scores)
{
    int jt = blockIdx.x, it = blockIdx.y;
    if (jt > it) return;
    int bh = blockIdx.z;
    int b = bh >> 4, h = bh & 15, kv = h >> 2;

    __shared__ float Qs[64][68];   // [d][i]
    __shared__ float Ks[64][68];   // [d][j]
    int tid = threadIdx.x;
#pragma unroll
    for (int l = 0; l < 4; l++) {
        int e = tid + l * 256;
        int r = e >> 4;
        int c = (e & 15) << 2;
        float4 a = *(const float4*)(q + (long)(b * CS + it * 64 + r) * (CNH * CDH) + h * CDH + c);
        Qs[c][r] = a.x; Qs[c + 1][r] = a.y; Qs[c + 2][r] = a.z; Qs[c + 3][r] = a.w;
        float4 bb = *(const float4*)(k + (long)(b * CS + jt * 64 + r) * (CNKV * CDH) + kv * CDH + c);
        Ks[c][r] = bb.x; Ks[c + 1][r] = bb.y; Ks[c + 2][r] = bb.z; Ks[c + 3][r] = bb.w;
    }
    __syncthreads();

    int ti = (tid >> 4) << 2;
    int tj = (tid & 15) << 2;
    float acc[4][4] = {};
#pragma unroll 8
    for (int d = 0; d < 64; d++) {
        float4 a = *(const float4*)&Qs[d][ti];
        float4 bb = *(const float4*)&Ks[d][tj];
        float af[4] = {a.x, a.y, a.z, a.w};
        float bf[4] = {bb.x, bb.y, bb.z, bb.w};
#pragma unroll
        for (int i = 0; i < 4; i++)
#pragma unroll
            for (int j = 0; j < 4; j++) acc[i][j] += af[i] * bf[j];
    }
    const float scale = 0.125f;  // DH^-0.5
#pragma unroll
    for (int i = 0; i < 4; i++) {
        long rbase = ((long)bh * CS + it * 64 + ti + i) * CS + jt * 64 + tj;
#pragma unroll
        for (int j = 0; j < 4; j++) scores[rbase + j] = acc[i][j] * scale;
    }
}

// ---------------- causal masked softmax, in-place; zero-pads tail of diag tile ----------------
__global__ __launch_bounds__(256) void attn_softmax_kernel(
    float* __restrict__ scores, const int* __restrict__ amask)
{
    int i = blockIdx.x, bh = blockIdx.y;
    int b = bh >> 4;
    float* row = scores + ((long)bh * CS + i) * CS;
    int len = i + 1;
    int jceil = ((i >> 6) + 1) << 6;
    int tid = threadIdx.x;
    __shared__ float red[256];

    float mx = -1e30f;
    for (int j = tid; j < len; j += 256) {
        float v = (amask[b * CS + j] > 0) ? row[j] : -1e9f;
        mx = fmaxf(mx, v);
    }
    red[tid] = mx; __syncthreads();
    for (int s = 128; s > 0; s >>= 1) {
        if (tid < s) red[tid] = fmaxf(red[tid], red[tid + s]);
        __syncthreads();
    }
    float M = red[0]; __syncthreads();

    float sum = 0.f;
    for (int j = tid; j < len; j += 256) {
        float v = (amask[b * CS + j] > 0) ? row[j] : -1e9f;
        sum += expf(v - M);
    }
    red[tid] = sum; __syncthreads();
    for (int s = 128; s > 0; s >>= 1) {
        if (tid < s) red[tid] += red[tid + s];
        __syncthreads();
    }
    float inv = 1.0f / red[0];

    for (int j = tid; j < len; j += 256) {
        float v = (amask[b * CS + j] > 0) ? row[j] : -1e9f;
        row[j] = expf(v - M) * inv;
    }
    for (int j = len + tid; j < jceil; j += 256) row[j] = 0.f;
}

// ---------------- PV: out[64 x 64] per (it, bh), looping causal j-tiles ----------------
__global__ __launch_bounds__(256) void attn_pv_kernel(
    const float* __restrict__ probs, const float* __restrict__ v, float* __restrict__ attn)
{
    int it = blockIdx.x;
    int bh = blockIdx.y;
    int b = bh >> 4, h = bh & 15, kv = h >> 2;

    __shared__ float Ps[64][68];  // [j][i]
    __shared__ float Vs[64][68];  // [j][d]
    int tid = threadIdx.x;
    int ti = (tid >> 4) << 2;
    int td = (tid & 15) << 2;
    float acc[4][4] = {};

    for (int jt = 0; jt <= it; jt++) {
#pragma unroll
        for (int l = 0; l < 4; l++) {
            int e = tid + l * 256;
            int r = e >> 4;
            int c = (e & 15) << 2;
            float4 p = *(const float4*)(probs + ((long)bh * CS + it * 64 + r) * CS + jt * 64 + c);
            Ps[c][r] = p.x; Ps[c + 1][r] = p.y; Ps[c + 2][r] = p.z; Ps[c + 3][r] = p.w;
            float4 vv = *(const float4*)(v + (long)(b * CS + jt * 64 + r) * (CNKV * CDH) + kv * CDH + c);
            *(float4*)&Vs[r][c] = vv;
        }
        __syncthreads();
#pragma unroll 8
        for (int jj = 0; jj < 64; jj++) {
            float4 a = *(const float4*)&Ps[jj][ti];
            float4 bb = *(const float4*)&Vs[jj][td];
            float af[4] = {a.x, a.y, a.z, a.w};
            float bf[4] = {bb.x, bb.y, bb.z, bb.w};
#pragma unroll
            for (int i = 0; i < 4; i++)
#pragma unroll
                for (int j = 0; j < 4; j++) acc[i][j] += af[i] * bf[j];
        }
        __syncthreads();
    }
#pragma unroll
    for (int i = 0; i < 4; i++) {
        long rbase = (long)(b * CS + it * 64 + ti + i) * CH + h * CDH + td;
#pragma unroll
        for (int j = 0; j < 4; j++) attn[rbase + j] = acc[i][j];
    }
}

// ---------------- MoE gating: softmax over 8 logits + top-2 ----------------
__global__ __launch_bounds__(128) void gate_kernel(
    const float* __restrict__ h2, const float* __restrict__ gw,
    int* __restrict__ topi, float* __restrict__ topw)
{
    int t = blockIdx.x;
    int tid = threadIdx.x;
    float p[8] = {};
    for (int hh = tid; hh < CH; hh += 128) {
        float x = h2[(long)t * CH + hh];
        const float* g = gw + hh * CE;
#pragma unroll
        for (int e = 0; e < 8; e++) p[e] += x * g[e];
    }
    __shared__ float red[128 * 8];
#pragma unroll
    for (int e = 0; e < 8; e++) red[tid * 8 + e] = p[e];
    __syncthreads();
    for (int s = 64; s > 0; s >>= 1) {
        if (tid < s)
#pragma unroll
            for (int e = 0; e < 8; e++) red[tid * 8 + e] += red[(tid + s) * 8 + e];
        __syncthreads();
    }
    if (tid == 0) {
        float lg[8], pr[8];
        float m = -1e30f;
#pragma unroll
        for (int e = 0; e < 8; e++) { lg[e] = red[e]; m = fmaxf(m, lg[e]); }
        float sum = 0.f;
#pragma unroll
        for (int e = 0; e < 8; e++) { pr[e] = expf(lg[e] - m); sum += pr[e]; }
        float inv = 1.0f / sum;
#pragma unroll
        for (int e = 0; e < 8; e++) pr[e] *= inv;
        int i0 = 0;
#pragma unroll
        for (int e = 1; e < 8; e++) if (pr[e] > pr[i0]) i0 = e;
        int i1 = -1;
#pragma unroll
        for (int e = 0; e < 8; e++) {
            if (e == i0) continue;
            if (i1 < 0 || pr[e] > pr[i1]) i1 = e;
        }
        topi[t * 2] = i0; topi[t * 2 + 1] = i1;
        topw[t * 2] = pr[i0]; topw[t * 2 + 1] = pr[i1];
    }
}

// ---------------- per-expert token compaction + prefix offsets (one block) ----------------
__global__ __launch_bounds__(256) void route_kernel(
    const int* __restrict__ topi, const float* __restrict__ topw,
    int* __restrict__ tok, float* __restrict__ etw,
    int* __restrict__ cnt, int* __restrict__ off)
{
    int e = threadIdx.x >> 5;      // warp = expert
    int lane = threadIdx.x & 31;
    int count = 0;
    for (int base = 0; base < CT; base += 32) {
        int t = base + lane;
        int i0 = topi[t * 2], i1 = topi[t * 2 + 1];
        bool sel = (i0 == e) || (i1 == e);
        float w = (i0 == e) ? topw[t * 2] : topw[t * 2 + 1];
        unsigned m = __ballot_sync(0xFFFFFFFFu, sel);
        int pos = count + __popc(m & ((1u << lane) - 1u));
        if (sel) {
            tok[e * CT + pos] = t;
            etw[e * CT + pos] = w;
        }
        count += __popc(m);
    }
    if (lane == 0) cnt[e] = count;
    __syncthreads();
    if (threadIdx.x == 0) {
        int s = 0;
        for (int i = 0; i < CE; i++) { off[i] = s; s += cnt[i]; }
        off[CE] = s;
    }
}

// ---------------- GEGLU over compacted slots: mid1 = gelu_tanh(mid1) * mid2 ----------------
__global__ __launch_bounds__(256) void glu_kernel(
    float* __restrict__ a, const float* __restrict__ b, const int* __restrict__ off)
{
    int row = blockIdx.y;
    if (row >= off[CE]) return;
    long idx = (long)row * CI + blockIdx.x * 256 + threadIdx.x;
    float x = a[idx];
    float g = 0.5f * x * (1.0f + tanhf(0.7978845608028654f * (x + 0.044715f * x * x * x)));
    a[idx] = g * b[idx];
}

// ---------------- zero fill ----------------
__global__ __launch_bounds__(256) void zero_kernel(float* __restrict__ p)
{
    p[(long)blockIdx.x * 256 + threadIdx.x] = 0.f;
}

// ---------------- host orchestration ----------------
#define SYMADDR(var, ptr) do { void* _p = nullptr; cudaGetSymbolAddress(&_p, var); ptr = (decltype(ptr))_p; } while (0)

extern "C" void kernel_launch(void* const* d_in, const int* in_sizes, int n_in,
                              void* d_out, int out_size)
{
    const float* hidden   = (const float*)d_in[0];
    const int*   amask    = (const int*)d_in[1];
    const int*   posids   = (const int*)d_in[2];
    const float* q_w      = (const float*)d_in[3];
    const float* k_w      = (const float*)d_in[4];
    const float* v_w      = (const float*)d_in[5];
    const float* o_w      = (const float*)d_in[6];
    const float* pre_attn = (const float*)d_in[7];
    const float* post_attn= (const float*)d_in[8];
    const float* pre_moe  = (const float*)d_in[9];
    const float* post_moe = (const float*)d_in[10];
    const float* gate_w   = (const float*)d_in[11];
    const float* w_in     = (const float*)d_in[12];
    const float* w_v      = (const float*)d_in[13];
    const float* w_out    = (const float*)d_in[14];
    float* out = (float*)d_out;

    float *hnorm, *q, *k, *v, *scores, *attn, *aproj, *x, *h2, *mid1, *mid2, *moe, *topw, *etw;
    int *topi, *tok, *cnt, *off;
    SYMADDR(g_hnorm, hnorm); SYMADDR(g_q, q); SYMADDR(g_k, k); SYMADDR(g_v, v);
    SYMADDR(g_scores, scores); SYMADDR(g_attn, attn); SYMADDR(g_aproj, aproj);
    SYMADDR(g_x, x); SYMADDR(g_h2, h2); SYMADDR(g_mid1, mid1); SYMADDR(g_mid2, mid2);
    SYMADDR(g_moe, moe); SYMADDR(g_topi, topi); SYMADDR(g_topw, topw);
    SYMADDR(g_tok, tok); SYMADDR(g_etw, etw); SYMADDR(g_cnt, cnt); SYMADDR(g_off, off);

    // 1) pre-attn rmsnorm
    rmsnorm_kernel<<<CT, 256>>>(hidden, pre_attn, nullptr, hnorm);

    // 2) fused QKV projections (one launch)
    qkv_kernel<<<dim3(12, CT / 128), 256>>>(hnorm, q_w, k_w, v_w, q, k, v);

    // 3) RoPE
    rope_kernel<<<(CT * 20 * 32) / 256, 256>>>(q, k, posids);

    // 4) attention: scores (causal tiles) -> softmax -> PV
    attn_score_kernel<<<dim3(CS / 64, CS / 64, CB * CNH), 256>>>(q, k, scores);
    attn_softmax_kernel<<<dim3(CS, CB * CNH), 256>>>(scores, amask);
    attn_pv_kernel<<<dim3(CS / 64, CB * CNH), 256>>>(scores, v, attn);

    // 5) output projection + post-attn rmsnorm + residual
    gemm_plain_kernel<<<dim3(CH / 128, CT / 128), 256>>>(attn, o_w, aproj, CT, CH, CH);
    rmsnorm_kernel<<<CT, 256>>>(aproj, post_attn, hidden, x);

    // 6) pre-moe rmsnorm
    rmsnorm_kernel<<<CT, 256>>>(x, pre_moe, nullptr, h2);

    // 7) gating + routing (compaction + prefix offsets)
    gate_kernel<<<CT, 128>>>(h2, gate_w, topi, topw);
    route_kernel<<<1, 256>>>(topi, topw, tok, etw, cnt, off);

    // 8) sparse MoE: all experts concurrent, bf16x3 tensor-core GEMMs
    zero_kernel<<<(CT * CH) / 256, 256>>>(moe);
    moe_stage1_kernel<<<dim3(CI / 128, CT / 128, CE * 2), 256>>>(
        h2, w_in, w_v, mid1, mid2, tok, cnt, off);
    glu_kernel<<<dim3(CI / 256, CSLOTS), 256>>>(mid1, mid2, off);
    moe_stage2_kernel<<<dim3(CH / 128, CT / 128, CE), 256>>>(
        mid1, w_out, moe, tok, etw, cnt, off);

    // 9) post-moe rmsnorm + residual -> output
    rmsnorm_kernel<<<CT, 256>>>(moe, post_moe, x, out);
}

// round 11
// speedup vs baseline: 5.5894x; 1.0483x over previous
#include <cuda_runtime.h>
#include <math.h>
#include <stdint.h>

// ---------------- problem constants ----------------
constexpr int CB   = 2;
constexpr int CS   = 1024;
constexpr int CH   = 1024;
constexpr int CNH  = 16;
constexpr int CNKV = 4;
constexpr int CDH  = 64;
constexpr int CI   = 4096;
constexpr int CE   = 8;
constexpr int CT   = CB * CS;          // 2048 tokens
constexpr int CSLOTS = 2 * CT;         // total (token, expert) slots
constexpr float CEPS = 1e-5f;

// ---------------- device scratch ----------------
__device__ float g_hnorm[CT * CH];
__device__ float g_q[CT * CNH * CDH];
__device__ float g_k[CT * CNKV * CDH];
__device__ float g_v[CT * CNKV * CDH];
__device__ float g_attn[CT * CH];
__device__ float g_aproj[CT * CH];
__device__ float g_x[CT * CH];
__device__ float g_h2[CT * CH];
__device__ int   g_topi[CT * 2];
__device__ float g_topw[CT * 2];
__device__ int   g_tok[CE * CT];
__device__ float g_etw[CE * CT];
__device__ int   g_cnt[CE];
__device__ int   g_off[CE + 1];
__device__ float g_mid1[(long)CSLOTS * CI];   // 64 MB
__device__ float g_mid2[(long)CSLOTS * CI];   // 64 MB
__device__ float g_moe[CT * CH];

// ---------------- rmsnorm (optionally + residual) ----------------
__global__ __launch_bounds__(256) void rmsnorm_kernel(
    const float* __restrict__ in, const float* __restrict__ sc,
    const float* __restrict__ resid, float* __restrict__ out)
{
    long row = blockIdx.x;
    const float* x = in + row * CH;
    int tid = threadIdx.x;
    float v[4];
    float ss = 0.f;
#pragma unroll
    for (int u = 0; u < 4; u++) {
        v[u] = x[tid + u * 256];
        ss += v[u] * v[u];
    }
    __shared__ float red[256];
    red[tid] = ss;
    __syncthreads();
    for (int s = 128; s > 0; s >>= 1) {
        if (tid < s) red[tid] += red[tid + s];
        __syncthreads();
    }
    float r = rsqrtf(red[0] * (1.0f / CH) + CEPS);
#pragma unroll
    for (int u = 0; u < 4; u++) {
        int h = tid + u * 256;
        float o = v[u] * r * sc[h];
        if (resid) o += resid[row * CH + h];
        out[row * CH + h] = o;
    }
}

// ================= bf16x3 split tensor-core GEMM core =================
// (unchanged from passing R9 kernel)

__device__ __forceinline__ uint32_t bf16_rne_bits(float x) {
    uint32_t u = __float_as_uint(x);
    uint32_t r = u + 0x7FFFu + ((u >> 16) & 1u);
    return r & 0xFFFF0000u;
}

__device__ __forceinline__ void split_pack(float x0, float x1, uint32_t& hi, uint32_t& lo) {
    uint32_t h0b = bf16_rne_bits(x0);
    uint32_t h1b = bf16_rne_bits(x1);
    float l0 = x0 - __uint_as_float(h0b);
    float l1 = x1 - __uint_as_float(h1b);
    uint32_t l0b = bf16_rne_bits(l0);
    uint32_t l1b = bf16_rne_bits(l1);
    hi = (h0b >> 16) | (h1b & 0xFFFF0000u);
    lo = (l0b >> 16) | (l1b & 0xFFFF0000u);
}

__device__ __forceinline__ void mma_bf16(float* c, const uint32_t* a, const uint32_t* b) {
    asm volatile(
        "mma.sync.aligned.m16n8k16.row.col.f32.bf16.bf16.f32 "
        "{%0,%1,%2,%3}, {%4,%5,%6,%7}, {%8,%9}, {%0,%1,%2,%3};"
        : "+f"(c[0]), "+f"(c[1]), "+f"(c[2]), "+f"(c[3])
        : "r"(a[0]), "r"(a[1]), "r"(a[2]), "r"(a[3]), "r"(b[0]), "r"(b[1]));
}

template <bool GATHER, bool SCATTER>
__device__ __forceinline__ void mma_gemm_block(
    const float* __restrict__ A, int lda,
    const float* __restrict__ B, int ldb,
    float* __restrict__ C, int ldc,
    int M, int K,
    int row_base, int col_base,
    const int* __restrict__ row_idx, const float* __restrict__ row_w)
{
    __shared__ uint32_t Ahi[2][128][12], Alo[2][128][12];   // [m][k/2], stride 12
    __shared__ uint32_t Bhi[2][8][136],  Blo[2][8][136];    // [k/2][n], stride 136

    int tid  = threadIdx.x;
    int lane = tid & 31;
    int warp = tid >> 5;
    int g  = lane >> 2;   // 0..7
    int t4 = lane & 3;    // 0..3
    int m_warp = (warp & 3) * 32;
    int n_warp = (warp >> 2) * 64;

    int m_l = tid >> 1;
    int kq  = (tid & 1) * 8;
    int kq2 = (tid & 1) * 4;
    int ar  = row_base + m_l;
    bool aval = ar < M;
    const float* aptr = A;
    if (aval) {
        int r = GATHER ? row_idx[ar] : ar;
        aptr = A + (long)r * lda + kq;
    }
    int k2_l = tid >> 5;          // 0..7
    int n_l  = (tid & 31) * 4;    // 0..124
    const float* bptr = B + (long)(2 * k2_l) * ldb + col_base + n_l;

    float acc[2][8][4];
#pragma unroll
    for (int i = 0; i < 2; i++)
#pragma unroll
        for (int j = 0; j < 8; j++)
#pragma unroll
            for (int l = 0; l < 4; l++) acc[i][j][l] = 0.f;

    float4 pa0, pa1, pb0, pb1;

    pa0 = make_float4(0.f, 0.f, 0.f, 0.f); pa1 = pa0;
    if (aval) { pa0 = *(const float4*)(aptr); pa1 = *(const float4*)(aptr + 4); }
    pb0 = *(const float4*)(bptr);
    pb1 = *(const float4*)(bptr + ldb);
    {
        uint32_t h, l;
        split_pack(pa0.x, pa0.y, h, l); Ahi[0][m_l][kq2 + 0] = h; Alo[0][m_l][kq2 + 0] = l;
        split_pack(pa0.z, pa0.w, h, l); Ahi[0][m_l][kq2 + 1] = h; Alo[0][m_l][kq2 + 1] = l;
        split_pack(pa1.x, pa1.y, h, l); Ahi[0][m_l][kq2 + 2] = h; Alo[0][m_l][kq2 + 2] = l;
        split_pack(pa1.z, pa1.w, h, l); Ahi[0][m_l][kq2 + 3] = h; Alo[0][m_l][kq2 + 3] = l;
        split_pack(pb0.x, pb1.x, h, l); Bhi[0][k2_l][n_l + 0] = h; Blo[0][k2_l][n_l + 0] = l;
        split_pack(pb0.y, pb1.y, h, l); Bhi[0][k2_l][n_l + 1] = h; Blo[0][k2_l][n_l + 1] = l;
        split_pack(pb0.z, pb1.z, h, l); Bhi[0][k2_l][n_l + 2] = h; Blo[0][k2_l][n_l + 2] = l;
        split_pack(pb0.w, pb1.w, h, l); Bhi[0][k2_l][n_l + 3] = h; Blo[0][k2_l][n_l + 3] = l;
    }
    __syncthreads();

    int KT = K >> 4;
    for (int kt = 0; kt < KT; kt++) {
        if (kt + 1 < KT) {
            long ko = (long)(kt + 1) * 16;
            pa0 = make_float4(0.f, 0.f, 0.f, 0.f); pa1 = pa0;
            if (aval) { pa0 = *(const float4*)(aptr + ko); pa1 = *(const float4*)(aptr + ko + 4); }
            const float* bp = bptr + ko * ldb;
            pb0 = *(const float4*)(bp);
            pb1 = *(const float4*)(bp + ldb);
        }

        int buf = kt & 1;
        uint32_t ah[2][4], al[2][4];
#pragma unroll
        for (int mf = 0; mf < 2; mf++) {
            int mb = m_warp + mf * 16 + g;
            ah[mf][0] = Ahi[buf][mb][t4];         al[mf][0] = Alo[buf][mb][t4];
            ah[mf][1] = Ahi[buf][mb + 8][t4];     al[mf][1] = Alo[buf][mb + 8][t4];
            ah[mf][2] = Ahi[buf][mb][t4 + 4];     al[mf][2] = Alo[buf][mb][t4 + 4];
            ah[mf][3] = Ahi[buf][mb + 8][t4 + 4]; al[mf][3] = Alo[buf][mb + 8][t4 + 4];
        }
        uint32_t bh[8][2], bl[8][2];
#pragma unroll
        for (int nf = 0; nf < 8; nf++) {
            int nb = n_warp + nf * 8 + g;
            bh[nf][0] = Bhi[buf][t4][nb];     bl[nf][0] = Blo[buf][t4][nb];
            bh[nf][1] = Bhi[buf][t4 + 4][nb]; bl[nf][1] = Blo[buf][t4 + 4][nb];
        }
#pragma unroll
        for (int mf = 0; mf < 2; mf++)
#pragma unroll
            for (int nf = 0; nf < 8; nf++) {
                mma_bf16(acc[mf][nf], ah[mf], bh[nf]);
                mma_bf16(acc[mf][nf], al[mf], bh[nf]);
                mma_bf16(acc[mf][nf], ah[mf], bl[nf]);
            }

        if (kt + 1 < KT) {
            int nb = (kt + 1) & 1;
            uint32_t h, l;
            split_pack(pa0.x, pa0.y, h, l); Ahi[nb][m_l][kq2 + 0] = h; Alo[nb][m_l][kq2 + 0] = l;
            split_pack(pa0.z, pa0.w, h, l); Ahi[nb][m_l][kq2 + 1] = h; Alo[nb][m_l][kq2 + 1] = l;
            split_pack(pa1.x, pa1.y, h, l); Ahi[nb][m_l][kq2 + 2] = h; Alo[nb][m_l][kq2 + 2] = l;
            split_pack(pa1.z, pa1.w, h, l); Ahi[nb][m_l][kq2 + 3] = h; Alo[nb][m_l][kq2 + 3] = l;
            split_pack(pb0.x, pb1.x, h, l); Bhi[nb][k2_l][n_l + 0] = h; Blo[nb][k2_l][n_l + 0] = l;
            split_pack(pb0.y, pb1.y, h, l); Bhi[nb][k2_l][n_l + 1] = h; Blo[nb][k2_l][n_l + 1] = l;
            split_pack(pb0.z, pb1.z, h, l); Bhi[nb][k2_l][n_l + 2] = h; Blo[nb][k2_l][n_l + 2] = l;
            split_pack(pb0.w, pb1.w, h, l); Bhi[nb][k2_l][n_l + 3] = h; Blo[nb][k2_l][n_l + 3] = l;
            __syncthreads();
        }
    }

#pragma unroll
    for (int mf = 0; mf < 2; mf++) {
        int r0 = row_base + m_warp + mf * 16 + g;
        int r1 = r0 + 8;
        bool v0 = r0 < M, v1 = r1 < M;
        if (!SCATTER) {
#pragma unroll
            for (int nf = 0; nf < 8; nf++) {
                int c = col_base + n_warp + nf * 8 + t4 * 2;
                if (v0) *(float2*)&C[(long)r0 * ldc + c] = make_float2(acc[mf][nf][0], acc[mf][nf][1]);
                if (v1) *(float2*)&C[(long)r1 * ldc + c] = make_float2(acc[mf][nf][2], acc[mf][nf][3]);
            }
        } else {
            int tk0 = 0, tk1 = 0; float w0 = 0.f, w1 = 0.f;
            if (v0) { tk0 = row_idx[r0]; w0 = row_w[r0]; }
            if (v1) { tk1 = row_idx[r1]; w1 = row_w[r1]; }
#pragma unroll
            for (int nf = 0; nf < 8; nf++) {
                int c = col_base + n_warp + nf * 8 + t4 * 2;
                if (v0) {
                    atomicAdd(&C[(long)tk0 * ldc + c],     w0 * acc[mf][nf][0]);
                    atomicAdd(&C[(long)tk0 * ldc + c + 1], w0 * acc[mf][nf][1]);
                }
                if (v1) {
                    atomicAdd(&C[(long)tk1 * ldc + c],     w1 * acc[mf][nf][2]);
                    atomicAdd(&C[(long)tk1 * ldc + c + 1], w1 * acc[mf][nf][3]);
                }
            }
        }
    }
}

// ---------------- fused QKV projection (one launch) ----------------
__global__ __launch_bounds__(256) void qkv_kernel(
    const float* __restrict__ hnorm,
    const float* __restrict__ qw, const float* __restrict__ kw, const float* __restrict__ vw,
    float* __restrict__ q, float* __restrict__ k, float* __restrict__ v)
{
    int x = blockIdx.x;   // 0..11
    const float* B; float* C; int ld; int col;
    if (x < 8)       { B = qw; C = q; ld = CNH * CDH;  col = x * 128; }
    else if (x < 10) { B = kw; C = k; ld = CNKV * CDH; col = (x - 8) * 128; }
    else             { B = vw; C = v; ld = CNKV * CDH; col = (x - 10) * 128; }
    mma_gemm_block<false, false>(hnorm, CH, B, ld, C, ld, CT, CH,
                                 blockIdx.y * 128, col, nullptr, nullptr);
}

// ---------------- plain GEMM (O projection) ----------------
__global__ __launch_bounds__(256) void gemm_plain_kernel(
    const float* __restrict__ A, const float* __restrict__ B, float* __restrict__ C,
    int M, int N, int K)
{
    mma_gemm_block<false, false>(A, K, B, N, C, N, M, K,
                                 blockIdx.y * 128, blockIdx.x * 128, nullptr, nullptr);
}

// ---------------- MoE stage 1: gather-GEMM, all experts + both matrices ----------------
__global__ __launch_bounds__(256) void moe_stage1_kernel(
    const float* __restrict__ h2,
    const float* __restrict__ w_in, const float* __restrict__ w_v,
    float* __restrict__ mid1, float* __restrict__ mid2,
    const int* __restrict__ tok, const int* __restrict__ cnt, const int* __restrict__ off)
{
    int z = blockIdx.z;
    int e = z >> 1;
    int which = z & 1;
    int M = cnt[e];
    int row_base = blockIdx.y * 128;
    if (row_base >= M) return;
    const float* B = (which ? w_v : w_in) + (long)e * CH * CI;
    float* C = (which ? mid2 : mid1) + (long)off[e] * CI;
    mma_gemm_block<true, false>(h2, CH, B, CI, C, CI, M, CH,
                                row_base, blockIdx.x * 128, tok + e * CT, nullptr);
}

// ---------------- MoE stage 2: weighted scatter-GEMM, all experts ----------------
__global__ __launch_bounds__(256) void moe_stage2_kernel(
    const float* __restrict__ mid1, const float* __restrict__ w_out, float* __restrict__ moe,
    const int* __restrict__ tok, const float* __restrict__ etw,
    const int* __restrict__ cnt, const int* __restrict__ off)
{
    int e = blockIdx.z;
    int M = cnt[e];
    int row_base = blockIdx.y * 128;
    if (row_base >= M) return;
    const float* A = mid1 + (long)off[e] * CI;
    const float* B = w_out + (long)e * CI * CH;
    mma_gemm_block<false, true>(A, CI, B, CH, moe, CH, M, CI,
                                row_base, blockIdx.x * 128, tok + e * CT, etw + e * CT);
}

// ---------------- RoPE on q (16 heads) and k (4 heads) ----------------
__global__ __launch_bounds__(256) void rope_kernel(
    float* __restrict__ q, float* __restrict__ k, const int* __restrict__ pos)
{
    long idx = (long)blockIdx.x * 256 + threadIdx.x;   // token*20heads*32
    if (idx >= (long)CT * 20 * 32) return;
    int d = idx & 31;
    int hh = (int)((idx >> 5) % 20);
    int t = (int)(idx / (32 * 20));
    float p = (float)pos[t];
    float inv = powf(10000.0f, -((float)d) / 32.0f);
    float ang = p * inv;
    float c = cosf(ang), s = sinf(ang);
    float* ptr;
    if (hh < CNH) ptr = q + (long)t * (CNH * CDH) + hh * CDH;
    else          ptr = k + (long)t * (CNKV * CDH) + (hh - CNH) * CDH;
    float x1 = ptr[d], x2 = ptr[d + 32];
    ptr[d]      = x1 * c - x2 * s;
    ptr[d + 32] = x2 * c + x1 * s;
}

// ================= fused flash attention =================
// One block per (64-row q-tile, head). Online softmax, causal tiles only.
// Dyn SMEM: Qs[64][68] ([d][i]) | KP 64*68 (K as [d][j], then P as [i][j]) | Vs[64][68] ([j][d])
constexpr int FA_STRIDE = 68;
constexpr int FA_REGION = 64 * FA_STRIDE;               // 4352 floats
constexpr int FA_SMEM_BYTES = 3 * FA_REGION * 4;        // 52224 B

__global__ __launch_bounds__(256) void flash_attn_kernel(
    const float* __restrict__ q, const float* __restrict__ k, const float* __restrict__ v,
    const int* __restrict__ amask, float* __restrict__ attn)
{
    extern __shared__ float sm[];
    float* Qs = sm;
    float* KP = sm + FA_REGION;
    float* Vs = sm + 2 * FA_REGION;

    int it = (int)gridDim.x - 1 - (int)blockIdx.x;   // heavy tiles first
    int bh = blockIdx.y;
    int b = bh >> 4, h = bh & 15, kv = h >> 2;
    int tid = threadIdx.x;
    int ti = (tid >> 4) << 2;     // row base (0..60)
    int tj = (tid & 15) << 2;     // col / d base (0..60)

    // load Q tile transposed [d][i]
#pragma unroll
    for (int l = 0; l < 4; l++) {
        int e = tid + l * 256;
        int r = e >> 4;
        int c = (e & 15) << 2;
        float4 a = *(const float4*)(q + (long)(b * CS + it * 64 + r) * (CNH * CDH) + h * CDH + c);
        Qs[(c + 0) * FA_STRIDE + r] = a.x; Qs[(c + 1) * FA_STRIDE + r] = a.y;
        Qs[(c + 2) * FA_STRIDE + r] = a.z; Qs[(c + 3) * FA_STRIDE + r] = a.w;
    }

    float m_i[4], l_i[4], acc[4][4];
#pragma unroll
    for (int i = 0; i < 4; i++) {
        m_i[i] = -1e30f; l_i[i] = 0.f;
#pragma unroll
        for (int j = 0; j < 4; j++) acc[i][j] = 0.f;
    }

    for (int jt = 0; jt <= it; jt++) {
        __syncthreads();   // prev iter's KP/Vs reads done; also covers Qs stores on iter 0
        // load K transposed [d][j] and V [j][d]
#pragma unroll
        for (int l = 0; l < 4; l++) {
            int e = tid + l * 256;
            int r = e >> 4;
            int c = (e & 15) << 2;
            const float* kvbase = k + (long)(b * CS + jt * 64 + r) * (CNKV * CDH) + kv * CDH + c;
            float4 kk = *(const float4*)(kvbase);
            KP[(c + 0) * FA_STRIDE + r] = kk.x; KP[(c + 1) * FA_STRIDE + r] = kk.y;
            KP[(c + 2) * FA_STRIDE + r] = kk.z; KP[(c + 3) * FA_STRIDE + r] = kk.w;
            float4 vv = *(const float4*)(v + (long)(b * CS + jt * 64 + r) * (CNKV * CDH) + kv * CDH + c);
            *(float4*)&Vs[r * FA_STRIDE + c] = vv;
        }
        __syncthreads();

        // S = Q K^T  (4x4 per thread)
        float s[4][4] = {};
#pragma unroll 8
        for (int d = 0; d < 64; d++) {
            float4 a = *(const float4*)&Qs[d * FA_STRIDE + ti];
            float4 bb = *(const float4*)&KP[d * FA_STRIDE + tj];
            float af[4] = {a.x, a.y, a.z, a.w};
            float bf[4] = {bb.x, bb.y, bb.z, bb.w};
#pragma unroll
            for (int i = 0; i < 4; i++)
#pragma unroll
                for (int j = 0; j < 4; j++) s[i][j] += af[i] * bf[j];
        }

        // scale + mask (reference semantics: where(causal & amask>0, s*scale, -1e9))
        int ig0 = it * 64 + ti;
        int jg0 = jt * 64 + tj;
        int msk[4];
#pragma unroll
        for (int j = 0; j < 4; j++) msk[j] = amask[b * CS + jg0 + j];
#pragma unroll
        for (int i = 0; i < 4; i++)
#pragma unroll
            for (int j = 0; j < 4; j++) {
                bool valid = (jg0 + j <= ig0 + i) && (msk[j] > 0);
                s[i][j] = valid ? s[i][j] * 0.125f : -1e9f;
            }

        // online softmax update (16-lane row groups = half-warps)
        float p[4][4];
#pragma unroll
        for (int i = 0; i < 4; i++) {
            float mx = fmaxf(fmaxf(s[i][0], s[i][1]), fmaxf(s[i][2], s[i][3]));
#pragma unroll
            for (int d = 1; d < 16; d <<= 1)
                mx = fmaxf(mx, __shfl_xor_sync(0xFFFFFFFFu, mx, d));
            float nm = fmaxf(m_i[i], mx);
            float alpha = expf(m_i[i] - nm);
            float rs = 0.f;
#pragma unroll
            for (int j = 0; j < 4; j++) { p[i][j] = expf(s[i][j] - nm); rs += p[i][j]; }
#pragma unroll
            for (int d = 1; d < 16; d <<= 1)
                rs += __shfl_xor_sync(0xFFFFFFFFu, rs, d);
            l_i[i] = l_i[i] * alpha + rs;
            m_i[i] = nm;
#pragma unroll
            for (int j = 0; j < 4; j++) acc[i][j] *= alpha;
        }

        __syncthreads();   // done reading KP as K
        // store P row-major [i][j] — float4 across the row, conflict-free
#pragma unroll
        for (int i = 0; i < 4; i++)
            *(float4*)&KP[(ti + i) * FA_STRIDE + tj] =
                make_float4(p[i][0], p[i][1], p[i][2], p[i][3]);
        __syncthreads();

        // O += P @ V : per 4-j chunk, broadcast P rows + conflict-free V rows
#pragma unroll 4
        for (int jc = 0; jc < 64; jc += 4) {
            float4 pr[4], vr[4];
#pragma unroll
            for (int i = 0; i < 4; i++) pr[i] = *(const float4*)&KP[(ti + i) * FA_STRIDE + jc];
#pragma unroll
            for (int j = 0; j < 4; j++) vr[j] = *(const float4*)&Vs[(jc + j) * FA_STRIDE + tj];
#pragma unroll
            for (int i = 0; i < 4; i++) {
                float pf[4] = {pr[i].x, pr[i].y, pr[i].z, pr[i].w};
#pragma unroll
                for (int j = 0; j < 4; j++) {
                    acc[i][0] += pf[j] * vr[j].x;
                    acc[i][1] += pf[j] * vr[j].y;
                    acc[i][2] += pf[j] * vr[j].z;
                    acc[i][3] += pf[j] * vr[j].w;
                }
            }
        }
    }

    // normalize + write
#pragma unroll
    for (int i = 0; i < 4; i++) {
        float inv = 1.0f / l_i[i];
        float* dst = attn + (long)(b * CS + it * 64 + ti + i) * CH + h * CDH + tj;
        *(float4*)dst = make_float4(acc[i][0] * inv, acc[i][1] * inv,
                                    acc[i][2] * inv, acc[i][3] * inv);
    }
}

// ---------------- MoE gating: softmax over 8 logits + top-2 ----------------
__global__ __launch_bounds__(128) void gate_kernel(
    const float* __restrict__ h2, const float* __restrict__ gw,
    int* __restrict__ topi, float* __restrict__ topw)
{
    int t = blockIdx.x;
    int tid = threadIdx.x;
    float p[8] = {};
    for (int hh = tid; hh < CH; hh += 128) {
        float x = h2[(long)t * CH + hh];
        const float* g = gw + hh * CE;
#pragma unroll
        for (int e = 0; e < 8; e++) p[e] += x * g[e];
    }
    __shared__ float red[128 * 8];
#pragma unroll
    for (int e = 0; e < 8; e++) red[tid * 8 + e] = p[e];
    __syncthreads();
    for (int s = 64; s > 0; s >>= 1) {
        if (tid < s)
#pragma unroll
            for (int e = 0; e < 8; e++) red[tid * 8 + e] += red[(tid + s) * 8 + e];
        __syncthreads();
    }
    if (tid == 0) {
        float lg[8], pr[8];
        float m = -1e30f;
#pragma unroll
        for (int e = 0; e < 8; e++) { lg[e] = red[e]; m = fmaxf(m, lg[e]); }
        float sum = 0.f;
#pragma unroll
        for (int e = 0; e < 8; e++) { pr[e] = expf(lg[e] - m); sum += pr[e]; }
        float inv = 1.0f / sum;
#pragma unroll
        for (int e = 0; e < 8; e++) pr[e] *= inv;
        int i0 = 0;
#pragma unroll
        for (int e = 1; e < 8; e++) if (pr[e] > pr[i0]) i0 = e;
        int i1 = -1;
#pragma unroll
        for (int e = 0; e < 8; e++) {
            if (e == i0) continue;
            if (i1 < 0 || pr[e] > pr[i1]) i1 = e;
        }
        topi[t * 2] = i0; topi[t * 2 + 1] = i1;
        topw[t * 2] = pr[i0]; topw[t * 2 + 1] = pr[i1];
    }
}

// ---------------- per-expert token compaction + prefix offsets (one block) ----------------
__global__ __launch_bounds__(256) void route_kernel(
    const int* __restrict__ topi, const float* __restrict__ topw,
    int* __restrict__ tok, float* __restrict__ etw,
    int* __restrict__ cnt, int* __restrict__ off)
{
    int e = threadIdx.x >> 5;      // warp = expert
    int lane = threadIdx.x & 31;
    int count = 0;
    for (int base = 0; base < CT; base += 32) {
        int t = base + lane;
        int i0 = topi[t * 2], i1 = topi[t * 2 + 1];
        bool sel = (i0 == e) || (i1 == e);
        float w = (i0 == e) ? topw[t * 2] : topw[t * 2 + 1];
        unsigned m = __ballot_sync(0xFFFFFFFFu, sel);
        int pos = count + __popc(m & ((1u << lane) - 1u));
        if (sel) {
            tok[e * CT + pos] = t;
            etw[e * CT + pos] = w;
        }
        count += __popc(m);
    }
    if (lane == 0) cnt[e] = count;
    __syncthreads();
    if (threadIdx.x == 0) {
        int s = 0;
        for (int i = 0; i < CE; i++) { off[i] = s; s += cnt[i]; }
        off[CE] = s;
    }
}

// ---------------- GEGLU over compacted slots: mid1 = gelu_tanh(mid1) * mid2 ----------------
__global__ __launch_bounds__(256) void glu_kernel(
    float* __restrict__ a, const float* __restrict__ b, const int* __restrict__ off)
{
    int row = blockIdx.y;
    if (row >= off[CE]) return;
    long idx = (long)row * CI + blockIdx.x * 256 + threadIdx.x;
    float x = a[idx];
    float g = 0.5f * x * (1.0f + tanhf(0.7978845608028654f * (x + 0.044715f * x * x * x)));
    a[idx] = g * b[idx];
}

// ---------------- zero fill ----------------
__global__ __launch_bounds__(256) void zero_kernel(float* __restrict__ p)
{
    p[(long)blockIdx.x * 256 + threadIdx.x] = 0.f;
}

// ---------------- host orchestration ----------------
#define SYMADDR(var, ptr) do { void* _p = nullptr; cudaGetSymbolAddress(&_p, var); ptr = (decltype(ptr))_p; } while (0)

extern "C" void kernel_launch(void* const* d_in, const int* in_sizes, int n_in,
                              void* d_out, int out_size)
{
    const float* hidden   = (const float*)d_in[0];
    const int*   amask    = (const int*)d_in[1];
    const int*   posids   = (const int*)d_in[2];
    const float* q_w      = (const float*)d_in[3];
    const float* k_w      = (const float*)d_in[4];
    const float* v_w      = (const float*)d_in[5];
    const float* o_w      = (const float*)d_in[6];
    const float* pre_attn = (const float*)d_in[7];
    const float* post_attn= (const float*)d_in[8];
    const float* pre_moe  = (const float*)d_in[9];
    const float* post_moe = (const float*)d_in[10];
    const float* gate_w   = (const float*)d_in[11];
    const float* w_in     = (const float*)d_in[12];
    const float* w_v      = (const float*)d_in[13];
    const float* w_out    = (const float*)d_in[14];
    float* out = (float*)d_out;

    float *hnorm, *q, *k, *v, *attn, *aproj, *x, *h2, *mid1, *mid2, *moe, *topw, *etw;
    int *topi, *tok, *cnt, *off;
    SYMADDR(g_hnorm, hnorm); SYMADDR(g_q, q); SYMADDR(g_k, k); SYMADDR(g_v, v);
    SYMADDR(g_attn, attn); SYMADDR(g_aproj, aproj);
    SYMADDR(g_x, x); SYMADDR(g_h2, h2); SYMADDR(g_mid1, mid1); SYMADDR(g_mid2, mid2);
    SYMADDR(g_moe, moe); SYMADDR(g_topi, topi); SYMADDR(g_topw, topw);
    SYMADDR(g_tok, tok); SYMADDR(g_etw, etw); SYMADDR(g_cnt, cnt); SYMADDR(g_off, off);

    // opt-in >48KB dynamic SMEM for the flash kernel (idempotent; non-stream call)
    cudaFuncSetAttribute((const void*)flash_attn_kernel,
                         cudaFuncAttributeMaxDynamicSharedMemorySize, FA_SMEM_BYTES);

    // 1) pre-attn rmsnorm
    rmsnorm_kernel<<<CT, 256>>>(hidden, pre_attn, nullptr, hnorm);

    // 2) fused QKV projections (one launch)
    qkv_kernel<<<dim3(12, CT / 128), 256>>>(hnorm, q_w, k_w, v_w, q, k, v);

    // 3) RoPE
    rope_kernel<<<(CT * 20 * 32) / 256, 256>>>(q, k, posids);

    // 4) fused flash attention (score + softmax + PV, no scores round-trip)
    flash_attn_kernel<<<dim3(CS / 64, CB * CNH), 256, FA_SMEM_BYTES>>>(
        q, k, v, amask, attn);

    // 5) output projection + post-attn rmsnorm + residual
    gemm_plain_kernel<<<dim3(CH / 128, CT / 128), 256>>>(attn, o_w, aproj, CT, CH, CH);
    rmsnorm_kernel<<<CT, 256>>>(aproj, post_attn, hidden, x);

    // 6) pre-moe rmsnorm
    rmsnorm_kernel<<<CT, 256>>>(x, pre_moe, nullptr, h2);

    // 7) gating + routing (compaction + prefix offsets)
    gate_kernel<<<CT, 128>>>(h2, gate_w, topi, topw);
    route_kernel<<<1, 256>>>(topi, topw, tok, etw, cnt, off);

    // 8) sparse MoE: all experts concurrent, bf16x3 tensor-core GEMMs
    zero_kernel<<<(CT * CH) / 256, 256>>>(moe);
    moe_stage1_kernel<<<dim3(CI / 128, CT / 128, CE * 2), 256>>>(
        h2, w_in, w_v, mid1, mid2, tok, cnt, off);
    glu_kernel<<<dim3(CI / 256, CSLOTS), 256>>>(mid1, mid2, off);
    moe_stage2_kernel<<<dim3(CH / 128, CT / 128, CE), 256>>>(
        mid1, w_out, moe, tok, etw, cnt, off);

    // 9) post-moe rmsnorm + residual -> output
    rmsnorm_kernel<<<CT, 256>>>(moe, post_moe, x, out);
}

// round 15
// speedup vs baseline: 6.4809x; 1.1595x over previous
#include <cuda_runtime.h>
#include <math.h>
#include <stdint.h>

// ---------------- problem constants ----------------
constexpr int CB   = 2;
constexpr int CS   = 1024;
constexpr int CH   = 1024;
constexpr int CNH  = 16;
constexpr int CNKV = 4;
constexpr int CDH  = 64;
constexpr int CI   = 4096;
constexpr int CE   = 8;
constexpr int CT   = CB * CS;          // 2048 tokens
constexpr int CSLOTS = 2 * CT;
constexpr float CEPS = 1e-5f;

// ---------------- device scratch ----------------
// fp32 buffers
__device__ float g_q[CT * CNH * CDH];
__device__ float g_k[CT * CNKV * CDH];
__device__ float g_v[CT * CNKV * CDH];
__device__ float g_aproj[CT * CH];
__device__ float g_x[CT * CH];
__device__ float g_h2[CT * CH];
__device__ float g_mid1[(long)CSLOTS * CI];
__device__ float g_mid2[(long)CSLOTS * CI];
__device__ float g_moe[CT * CH];
// routing
__device__ int   g_topi[CT * 2];
__device__ float g_topw[CT * 2];
__device__ int   g_tok[CE * CT];
__device__ float g_etw[CE * CT];
__device__ int   g_cnt[CE];
__device__ int   g_off[CE + 1];
// packed bf16x2 (even_k lo16, odd_k hi16) hi/lo split activations
__device__ uint32_t g_hnh[CT * 512], g_hnl[CT * 512];          // hnorm
__device__ uint32_t g_ath[CT * 512], g_atl[CT * 512];          // attn out
__device__ uint32_t g_h2h[CT * 512], g_h2l[CT * 512];          // h2
__device__ uint32_t g_m1h[(long)CSLOTS * 2048], g_m1l[(long)CSLOTS * 2048];  // glu out
// packed split weights
__device__ uint32_t g_qwh[512 * 1024], g_qwl[512 * 1024];
__device__ uint32_t g_kwh[512 * 256],  g_kwl[512 * 256];
__device__ uint32_t g_vwh[512 * 256],  g_vwl[512 * 256];
__device__ uint32_t g_owh[512 * 1024], g_owl[512 * 1024];
__device__ uint32_t g_wih[(long)8 * 512 * 4096],  g_wil[(long)8 * 512 * 4096];
__device__ uint32_t g_wvh[(long)8 * 512 * 4096],  g_wvl[(long)8 * 512 * 4096];
__device__ uint32_t g_woh[(long)8 * 2048 * 1024], g_wol[(long)8 * 2048 * 1024];

// ---------------- bf16 split helpers (verified R9 numerics) ----------------
__device__ __forceinline__ uint32_t bf16_rne_bits(float x) {
    uint32_t u = __float_as_uint(x);
    uint32_t r = u + 0x7FFFu + ((u >> 16) & 1u);
    return r & 0xFFFF0000u;
}
// x0 -> low 16 bits (even k), x1 -> high 16 bits (odd k)
__device__ __forceinline__ void split_pack(float x0, float x1, uint32_t& hi, uint32_t& lo) {
    uint32_t h0b = bf16_rne_bits(x0);
    uint32_t h1b = bf16_rne_bits(x1);
    float l0 = x0 - __uint_as_float(h0b);
    float l1 = x1 - __uint_as_float(h1b);
    uint32_t l0b = bf16_rne_bits(l0);
    uint32_t l1b = bf16_rne_bits(l1);
    hi = (h0b >> 16) | (h1b & 0xFFFF0000u);
    lo = (l0b >> 16) | (l1b & 0xFFFF0000u);
}

__device__ __forceinline__ void mma_bf16(float* c, const uint32_t* a, const uint32_t* b) {
    asm volatile(
        "mma.sync.aligned.m16n8k16.row.col.f32.bf16.bf16.f32 "
        "{%0,%1,%2,%3}, {%4,%5,%6,%7}, {%8,%9}, {%0,%1,%2,%3};"
        : "+f"(c[0]), "+f"(c[1]), "+f"(c[2]), "+f"(c[3])
        : "r"(a[0]), "r"(a[1]), "r"(a[2]), "r"(a[3]), "r"(b[0]), "r"(b[1]));
}

// ---------------- cp.async helpers (sm_80+, fine on compute_100) ----------------
__device__ __forceinline__ uint32_t smem_u32(const void* p) {
    uint32_t a;
    asm("{ .reg .u64 t; cvta.to.shared.u64 t, %1; cvt.u32.u64 %0, t; }" : "=r"(a) : "l"(p));
    return a;
}
__device__ __forceinline__ void cp16(uint32_t dst, const void* src, int sz) {
    asm volatile("cp.async.cg.shared.global [%0], [%1], 16, %2;"
                 :: "r"(dst), "l"(src), "r"(sz) : "memory");
}
#define CP_COMMIT() asm volatile("cp.async.commit_group;" ::: "memory")
#define CP_WAIT0()  asm volatile("cp.async.wait_group 0;" ::: "memory")

// ================= bf16x3 mma GEMM core, pre-split operands + cp.async =================
// 128x128 block tile, 256 threads (8 warps), warp tile 32x64, K-tile 16,
// double-buffered smem filled by cp.async; fragment loads + mma identical to R9.
// Operands are packed bf16x2 k-pairs: A [row][k/2] (lda2 = k-pairs/row),
// B [k/2][n] (ldb = n/row). 3 mmas per K-16 step: Ah*Bh + Al*Bh + Ah*Bl.
template <bool GATHER, bool SCATTER>
__device__ __forceinline__ void gemm_core(
    const uint32_t* __restrict__ Ah, const uint32_t* __restrict__ Al, int lda2,
    const uint32_t* __restrict__ Bh, const uint32_t* __restrict__ Bl, int ldb,
    float* __restrict__ C, int ldc,
    int M, int K,
    int row_base, int col_base,
    const int* __restrict__ row_idx, const float* __restrict__ row_w)
{
    __shared__ uint32_t Ahi[2][128][12], Alo[2][128][12];   // [m][k/2], stride 12
    __shared__ uint32_t Bhi[2][8][136],  Blo[2][8][136];    // [k/2][n], stride 136

    int tid  = threadIdx.x;
    int lane = tid & 31;
    int warp = tid >> 5;
    int g  = lane >> 2;
    int t4 = lane & 3;
    int m_warp = (warp & 3) * 32;
    int n_warp = (warp >> 2) * 64;

    // A loader: thread -> row tid>>1, 16B chunk (tid&1)
    int m_l = tid >> 1;
    int ac  = (tid & 1) * 4;            // uint32 offset within 8-wide row
    int ar  = row_base + m_l;
    bool aval = ar < M;
    const uint32_t* ah_src = Ah;
    const uint32_t* al_src = Al;
    if (aval) {
        int r = GATHER ? row_idx[ar] : ar;
        long ro = (long)r * lda2 + ac;
        ah_src = Ah + ro; al_src = Al + ro;
    }
    int azf = aval ? 16 : 0;
    // B loader: thread -> k-pair row tid>>5, 16B chunk tid&31
    int bkr = tid >> 5;
    int bc  = (tid & 31) * 4;
    const uint32_t* bh_src = Bh + (long)bkr * ldb + col_base + bc;
    const uint32_t* bl_src = Bl + (long)bkr * ldb + col_base + bc;

    float acc[2][8][4];
#pragma unroll
    for (int i = 0; i < 2; i++)
#pragma unroll
        for (int j = 0; j < 8; j++)
#pragma unroll
            for (int l = 0; l < 4; l++) acc[i][j][l] = 0.f;

    // issue tile 0
    {
        cp16(smem_u32(&Ahi[0][m_l][ac]), ah_src, azf);
        cp16(smem_u32(&Alo[0][m_l][ac]), al_src, azf);
        cp16(smem_u32(&Bhi[0][bkr][bc]), bh_src, 16);
        cp16(smem_u32(&Blo[0][bkr][bc]), bl_src, 16);
        CP_COMMIT();
    }

    int KT = K >> 4;
    for (int kt = 0; kt < KT; kt++) {
        CP_WAIT0();
        __syncthreads();
        if (kt + 1 < KT) {
            int nb = (kt + 1) & 1;
            long ao = (long)(kt + 1) * 8;
            long bo = (long)(kt + 1) * 8 * ldb;
            cp16(smem_u32(&Ahi[nb][m_l][ac]), ah_src + ao, azf);
            cp16(smem_u32(&Alo[nb][m_l][ac]), al_src + ao, azf);
            cp16(smem_u32(&Bhi[nb][bkr][bc]), bh_src + bo, 16);
            cp16(smem_u32(&Blo[nb][bkr][bc]), bl_src + bo, 16);
            CP_COMMIT();
        }

        int buf = kt & 1;
        // fragment loads (verified R9 layout; k packed in pairs)
        uint32_t ah[2][4], al[2][4];
#pragma unroll
        for (int mf = 0; mf < 2; mf++) {
            int mb = m_warp + mf * 16 + g;
            ah[mf][0] = Ahi[buf][mb][t4];         al[mf][0] = Alo[buf][mb][t4];
            ah[mf][1] = Ahi[buf][mb + 8][t4];     al[mf][1] = Alo[buf][mb + 8][t4];
            ah[mf][2] = Ahi[buf][mb][t4 + 4];     al[mf][2] = Alo[buf][mb][t4 + 4];
            ah[mf][3] = Ahi[buf][mb + 8][t4 + 4]; al[mf][3] = Alo[buf][mb + 8][t4 + 4];
        }
        uint32_t bh[8][2], bl[8][2];
#pragma unroll
        for (int nf = 0; nf < 8; nf++) {
            int nb2 = n_warp + nf * 8 + g;
            bh[nf][0] = Bhi[buf][t4][nb2];     bl[nf][0] = Blo[buf][t4][nb2];
            bh[nf][1] = Bhi[buf][t4 + 4][nb2]; bl[nf][1] = Blo[buf][t4 + 4][nb2];
        }
#pragma unroll
        for (int mf = 0; mf < 2; mf++)
#pragma unroll
            for (int nf = 0; nf < 8; nf++) {
                mma_bf16(acc[mf][nf], ah[mf], bh[nf]);
                mma_bf16(acc[mf][nf], al[mf], bh[nf]);
                mma_bf16(acc[mf][nf], ah[mf], bl[nf]);
            }
    }

    // ---- epilogue (verified R9) ----
#pragma unroll
    for (int mf = 0; mf < 2; mf++) {
        int r0 = row_base + m_warp + mf * 16 + g;
        int r1 = r0 + 8;
        bool v0 = r0 < M, v1 = r1 < M;
        if (!SCATTER) {
#pragma unroll
            for (int nf = 0; nf < 8; nf++) {
                int c = col_base + n_warp + nf * 8 + t4 * 2;
                if (v0) *(float2*)&C[(long)r0 * ldc + c] = make_float2(acc[mf][nf][0], acc[mf][nf][1]);
                if (v1) *(float2*)&C[(long)r1 * ldc + c] = make_float2(acc[mf][nf][2], acc[mf][nf][3]);
            }
        } else {
            int tk0 = 0, tk1 = 0; float w0 = 0.f, w1 = 0.f;
            if (v0) { tk0 = row_idx[r0]; w0 = row_w[r0]; }
            if (v1) { tk1 = row_idx[r1]; w1 = row_w[r1]; }
#pragma unroll
            for (int nf = 0; nf < 8; nf++) {
                int c = col_base + n_warp + nf * 8 + t4 * 2;
                if (v0) {
                    atomicAdd(&C[(long)tk0 * ldc + c],     w0 * acc[mf][nf][0]);
                    atomicAdd(&C[(long)tk0 * ldc + c + 1], w0 * acc[mf][nf][1]);
                }
                if (v1) {
                    atomicAdd(&C[(long)tk1 * ldc + c],     w1 * acc[mf][nf][2]);
                    atomicAdd(&C[(long)tk1 * ldc + c + 1], w1 * acc[mf][nf][3]);
                }
            }
        }
    }
}

// ---------------- weight convert: [2*kp_total][N] fp32 -> packed hi/lo [kp_total][N] ----------------
__global__ __launch_bounds__(256) void wconv_kernel(
    const float* __restrict__ in, uint32_t* __restrict__ oh, uint32_t* __restrict__ ol,
    long kp_total, int N)
{
    long idx = (long)blockIdx.x * 256 + threadIdx.x;
    long chunks = kp_total * (N >> 2);
    if (idx >= chunks) return;
    long kp = idx / (N >> 2);
    int  nq = (int)(idx % (N >> 2));
    const float* p0 = in + (2 * kp) * (long)N + 4 * nq;
    float4 a = *(const float4*)p0;
    float4 b = *(const float4*)(p0 + N);
    uint32_t h0, l0, h1, l1, h2, l2, h3, l3;
    split_pack(a.x, b.x, h0, l0);
    split_pack(a.y, b.y, h1, l1);
    split_pack(a.z, b.z, h2, l2);
    split_pack(a.w, b.w, h3, l3);
    long o = kp * (long)N + 4 * nq;
    *(uint4*)&oh[o] = make_uint4(h0, h1, h2, h3);
    *(uint4*)&ol[o] = make_uint4(l0, l1, l2, l3);
}

// ---------------- rmsnorm: optional residual, optional fp32 out, optional packed out ----------------
__global__ __launch_bounds__(256) void rmsnorm_kernel(
    const float* __restrict__ in, const float* __restrict__ sc,
    const float* __restrict__ resid, float* __restrict__ out,
    uint32_t* __restrict__ outh, uint32_t* __restrict__ outl)
{
    long row = blockIdx.x;
    int tid = threadIdx.x;
    float4 v = *(const float4*)(in + row * CH + tid * 4);
    float ss = v.x * v.x + v.y * v.y + v.z * v.z + v.w * v.w;
    __shared__ float red[256];
    red[tid] = ss;
    __syncthreads();
    for (int s = 128; s > 0; s >>= 1) {
        if (tid < s) red[tid] += red[tid + s];
        __syncthreads();
    }
    float r = rsqrtf(red[0] * (1.0f / CH) + CEPS);
    float4 s4 = *(const float4*)(sc + tid * 4);
    float o0 = v.x * r * s4.x, o1 = v.y * r * s4.y, o2 = v.z * r * s4.z, o3 = v.w * r * s4.w;
    if (resid) {
        float4 rr = *(const float4*)(resid + row * CH + tid * 4);
        o0 += rr.x; o1 += rr.y; o2 += rr.z; o3 += rr.w;
    }
    if (out) *(float4*)(out + row * CH + tid * 4) = make_float4(o0, o1, o2, o3);
    if (outh) {
        uint32_t h0, l0, h1, l1;
        split_pack(o0, o1, h0, l0);
        split_pack(o2, o3, h1, l1);
        *(uint2*)&outh[row * 512 + tid * 2] = make_uint2(h0, h1);
        *(uint2*)&outl[row * 512 + tid * 2] = make_uint2(l0, l1);
    }
}

// ---------------- GEMM wrappers ----------------
__global__ __launch_bounds__(256) void qkv_kernel(
    const uint32_t* __restrict__ hnh, const uint32_t* __restrict__ hnl,
    const uint32_t* __restrict__ qwh, const uint32_t* __restrict__ qwl,
    const uint32_t* __restrict__ kwh, const uint32_t* __restrict__ kwl,
    const uint32_t* __restrict__ vwh, const uint32_t* __restrict__ vwl,
    float* __restrict__ q, float* __restrict__ k, float* __restrict__ v)
{
    int x = blockIdx.x;
    const uint32_t *Bh, *Bl; float* C; int ld; int col;
    if (x < 8)       { Bh = qwh; Bl = qwl; C = q; ld = 1024; col = x * 128; }
    else if (x < 10) { Bh = kwh; Bl = kwl; C = k; ld = 256;  col = (x - 8) * 128; }
    else             { Bh = vwh; Bl = vwl; C = v; ld = 256;  col = (x - 10) * 128; }
    gemm_core<false, false>(hnh, hnl, 512, Bh, Bl, ld, C, ld, CT, CH,
                            blockIdx.y * 128, col, nullptr, nullptr);
}

__global__ __launch_bounds__(256) void oproj_kernel(
    const uint32_t* __restrict__ ath, const uint32_t* __restrict__ atl,
    const uint32_t* __restrict__ owh, const uint32_t* __restrict__ owl,
    float* __restrict__ aproj)
{
    gemm_core<false, false>(ath, atl, 512, owh, owl, CH, aproj, CH, CT, CH,
                            blockIdx.y * 128, blockIdx.x * 128, nullptr, nullptr);
}

__global__ __launch_bounds__(256) void moe_stage1_kernel(
    const uint32_t* __restrict__ h2h, const uint32_t* __restrict__ h2l,
    const uint32_t* __restrict__ wih, const uint32_t* __restrict__ wil,
    const uint32_t* __restrict__ wvh, const uint32_t* __restrict__ wvl,
    float* __restrict__ mid1, float* __restrict__ mid2,
    const int* __restrict__ tok, const int* __restrict__ cnt, const int* __restrict__ off)
{
    int z = blockIdx.z;
    int e = z >> 1;
    int which = z & 1;
    int M = cnt[e];
    int row_base = blockIdx.y * 128;
    if (row_base >= M) return;
    const uint32_t* Bh = (which ? wvh : wih) + (long)e * 512 * CI;
    const uint32_t* Bl = (which ? wvl : wil) + (long)e * 512 * CI;
    float* C = (which ? mid2 : mid1) + (long)off[e] * CI;
    gemm_core<true, false>(h2h, h2l, 512, Bh, Bl, CI, C, CI, M, CH,
                           row_base, blockIdx.x * 128, tok + e * CT, nullptr);
}

__global__ __launch_bounds__(256) void moe_stage2_kernel(
    const uint32_t* __restrict__ m1h, const uint32_t* __restrict__ m1l,
    const uint32_t* __restrict__ woh, const uint32_t* __restrict__ wol,
    float* __restrict__ moe,
    const int* __restrict__ tok, const float* __restrict__ etw,
    const int* __restrict__ cnt, const int* __restrict__ off)
{
    int e = blockIdx.z;
    int M = cnt[e];
    int row_base = blockIdx.y * 128;
    if (row_base >= M) return;
    const uint32_t* Ah = m1h + (long)off[e] * 2048;
    const uint32_t* Al = m1l + (long)off[e] * 2048;
    const uint32_t* Bh = woh + (long)e * 2048 * CH;
    const uint32_t* Bl = wol + (long)e * 2048 * CH;
    gemm_core<false, true>(Ah, Al, 2048, Bh, Bl, CH, moe, CH, M, CI,
                           row_base, blockIdx.x * 128, tok + e * CT, etw + e * CT);
}

// ---------------- RoPE ----------------
__global__ __launch_bounds__(256) void rope_kernel(
    float* __restrict__ q, float* __restrict__ k, const int* __restrict__ pos)
{
    long idx = (long)blockIdx.x * 256 + threadIdx.x;
    if (idx >= (long)CT * 20 * 32) return;
    int d = idx & 31;
    int hh = (int)((idx >> 5) % 20);
    int t = (int)(idx / (32 * 20));
    float p = (float)pos[t];
    float inv = powf(10000.0f, -((float)d) / 32.0f);
    float ang = p * inv;
    float c = cosf(ang), s = sinf(ang);
    float* ptr;
    if (hh < CNH) ptr = q + (long)t * (CNH * CDH) + hh * CDH;
    else          ptr = k + (long)t * (CNKV * CDH) + (hh - CNH) * CDH;
    float x1 = ptr[d], x2 = ptr[d + 32];
    ptr[d]      = x1 * c - x2 * s;
    ptr[d + 32] = x2 * c + x1 * s;
}

// ================= fused flash attention (R10-verified; packed output) =================
constexpr int FA_STRIDE = 68;
constexpr int FA_REGION = 64 * FA_STRIDE;
constexpr int FA_SMEM_BYTES = 3 * FA_REGION * 4;

__global__ __launch_bounds__(256) void flash_attn_kernel(
    const float* __restrict__ q, const float* __restrict__ k, const float* __restrict__ v,
    const int* __restrict__ amask,
    uint32_t* __restrict__ attnh, uint32_t* __restrict__ attnl)
{
    extern __shared__ float sm[];
    float* Qs = sm;
    float* KP = sm + FA_REGION;
    float* Vs = sm + 2 * FA_REGION;

    int it = (int)gridDim.x - 1 - (int)blockIdx.x;
    int bh = blockIdx.y;
    int b = bh >> 4, h = bh & 15, kv = h >> 2;
    int tid = threadIdx.x;
    int ti = (tid >> 4) << 2;
    int tj = (tid & 15) << 2;

#pragma unroll
    for (int l = 0; l < 4; l++) {
        int e = tid + l * 256;
        int r = e >> 4;
        int c = (e & 15) << 2;
        float4 a = *(const float4*)(q + (long)(b * CS + it * 64 + r) * (CNH * CDH) + h * CDH + c);
        Qs[(c + 0) * FA_STRIDE + r] = a.x; Qs[(c + 1) * FA_STRIDE + r] = a.y;
        Qs[(c + 2) * FA_STRIDE + r] = a.z; Qs[(c + 3) * FA_STRIDE + r] = a.w;
    }

    float m_i[4], l_i[4], acc[4][4];
#pragma unroll
    for (int i = 0; i < 4; i++) {
        m_i[i] = -1e30f; l_i[i] = 0.f;
#pragma unroll
        for (int j = 0; j < 4; j++) acc[i][j] = 0.f;
    }

    for (int jt = 0; jt <= it; jt++) {
        __syncthreads();
#pragma unroll
        for (int l = 0; l < 4; l++) {
            int e = tid + l * 256;
            int r = e >> 4;
            int c = (e & 15) << 2;
            const float* kvbase = k + (long)(b * CS + jt * 64 + r) * (CNKV * CDH) + kv * CDH + c;
            float4 kk = *(const float4*)(kvbase);
            KP[(c + 0) * FA_STRIDE + r] = kk.x; KP[(c + 1) * FA_STRIDE + r] = kk.y;
            KP[(c + 2) * FA_STRIDE + r] = kk.z; KP[(c + 3) * FA_STRIDE + r] = kk.w;
            float4 vv = *(const float4*)(v + (long)(b * CS + jt * 64 + r) * (CNKV * CDH) + kv * CDH + c);
            *(float4*)&Vs[r * FA_STRIDE + c] = vv;
        }
        __syncthreads();

        float s[4][4] = {};
#pragma unroll 8
        for (int d = 0; d < 64; d++) {
            float4 a = *(const float4*)&Qs[d * FA_STRIDE + ti];
            float4 bb = *(const float4*)&KP[d * FA_STRIDE + tj];
            float af[4] = {a.x, a.y, a.z, a.w};
            float bf[4] = {bb.x, bb.y, bb.z, bb.w};
#pragma unroll
            for (int i = 0; i < 4; i++)
#pragma unroll
                for (int j = 0; j < 4; j++) s[i][j] += af[i] * bf[j];
        }

        int ig0 = it * 64 + ti;
        int jg0 = jt * 64 + tj;
        int msk[4];
#pragma unroll
        for (int j = 0; j < 4; j++) msk[j] = amask[b * CS + jg0 + j];
#pragma unroll
        for (int i = 0; i < 4; i++)
#pragma unroll
            for (int j = 0; j < 4; j++) {
                bool valid = (jg0 + j <= ig0 + i) && (msk[j] > 0);
                s[i][j] = valid ? s[i][j] * 0.125f : -1e9f;
            }

        float p[4][4];
#pragma unroll
        for (int i = 0; i < 4; i++) {
            float mx = fmaxf(fmaxf(s[i][0], s[i][1]), fmaxf(s[i][2], s[i][3]));
#pragma unroll
            for (int d = 1; d < 16; d <<= 1)
                mx = fmaxf(mx, __shfl_xor_sync(0xFFFFFFFFu, mx, d));
            float nm = fmaxf(m_i[i], mx);
            float alpha = expf(m_i[i] - nm);
            float rs = 0.f;
#pragma unroll
            for (int j = 0; j < 4; j++) { p[i][j] = expf(s[i][j] - nm); rs += p[i][j]; }
#pragma unroll
            for (int d = 1; d < 16; d <<= 1)
                rs += __shfl_xor_sync(0xFFFFFFFFu, rs, d);
            l_i[i] = l_i[i] * alpha + rs;
            m_i[i] = nm;
#pragma unroll
            for (int j = 0; j < 4; j++) acc[i][j] *= alpha;
        }

        __syncthreads();
#pragma unroll
        for (int i = 0; i < 4; i++)
            *(float4*)&KP[(ti + i) * FA_STRIDE + tj] =
                make_float4(p[i][0], p[i][1], p[i][2], p[i][3]);
        __syncthreads();

#pragma unroll 4
        for (int jc = 0; jc < 64; jc += 4) {
            float4 pr[4], vr[4];
#pragma unroll
            for (int i = 0; i < 4; i++) pr[i] = *(const float4*)&KP[(ti + i) * FA_STRIDE + jc];
#pragma unroll
            for (int j = 0; j < 4; j++) vr[j] = *(const float4*)&Vs[(jc + j) * FA_STRIDE + tj];
#pragma unroll
            for (int i = 0; i < 4; i++) {
                float pf[4] = {pr[i].x, pr[i].y, pr[i].z, pr[i].w};
#pragma unroll
                for (int j = 0; j < 4; j++) {
                    acc[i][0] += pf[j] * vr[j].x;
                    acc[i][1] += pf[j] * vr[j].y;
                    acc[i][2] += pf[j] * vr[j].z;
                    acc[i][3] += pf[j] * vr[j].w;
                }
            }
        }
    }

    // normalize + packed-split write
#pragma unroll
    for (int i = 0; i < 4; i++) {
        float inv = 1.0f / l_i[i];
        float o0 = acc[i][0] * inv, o1 = acc[i][1] * inv;
        float o2 = acc[i][2] * inv, o3 = acc[i][3] * inv;
        uint32_t h0, l0, h1, l1;
        split_pack(o0, o1, h0, l0);
        split_pack(o2, o3, h1, l1);
        long rb = (long)(b * CS + it * 64 + ti + i) * 512 + ((h * CDH + tj) >> 1);
        *(uint2*)&attnh[rb] = make_uint2(h0, h1);
        *(uint2*)&attnl[rb] = make_uint2(l0, l1);
    }
}

// ---------------- MoE gating ----------------
__global__ __launch_bounds__(128) void gate_kernel(
    const float* __restrict__ h2, const float* __restrict__ gw,
    int* __restrict__ topi, float* __restrict__ topw)
{
    int t = blockIdx.x;
    int tid = threadIdx.x;
    float p[8] = {};
    for (int hh = tid; hh < CH; hh += 128) {
        float x = h2[(long)t * CH + hh];
        const float* g = gw + hh * CE;
#pragma unroll
        for (int e = 0; e < 8; e++) p[e] += x * g[e];
    }
    __shared__ float red[128 * 8];
#pragma unroll
    for (int e = 0; e < 8; e++) red[tid * 8 + e] = p[e];
    __syncthreads();
    for (int s = 64; s > 0; s >>= 1) {
        if (tid < s)
#pragma unroll
            for (int e = 0; e < 8; e++) red[tid * 8 + e] += red[(tid + s) * 8 + e];
        __syncthreads();
    }
    if (tid == 0) {
        float lg[8], pr[8];
        float m = -1e30f;
#pragma unroll
        for (int e = 0; e < 8; e++) { lg[e] = red[e]; m = fmaxf(m, lg[e]); }
        float sum = 0.f;
#pragma unroll
        for (int e = 0; e < 8; e++) { pr[e] = expf(lg[e] - m); sum += pr[e]; }
        float inv = 1.0f / sum;
#pragma unroll
        for (int e = 0; e < 8; e++) pr[e] *= inv;
        int i0 = 0;
#pragma unroll
        for (int e = 1; e < 8; e++) if (pr[e] > pr[i0]) i0 = e;
        int i1 = -1;
#pragma unroll
        for (int e = 0; e < 8; e++) {
            if (e == i0) continue;
            if (i1 < 0 || pr[e] > pr[i1]) i1 = e;
        }
        topi[t * 2] = i0; topi[t * 2 + 1] = i1;
        topw[t * 2] = pr[i0]; topw[t * 2 + 1] = pr[i1];
    }
}

// ---------------- routing ----------------
__global__ __launch_bounds__(256) void route_kernel(
    const int* __restrict__ topi, const float* __restrict__ topw,
    int* __restrict__ tok, float* __restrict__ etw,
    int* __restrict__ cnt, int* __restrict__ off)
{
    int e = threadIdx.x >> 5;
    int lane = threadIdx.x & 31;
    int count = 0;
    for (int base = 0; base < CT; base += 32) {
        int t = base + lane;
        int i0 = topi[t * 2], i1 = topi[t * 2 + 1];
        bool sel = (i0 == e) || (i1 == e);
        float w = (i0 == e) ? topw[t * 2] : topw[t * 2 + 1];
        unsigned m = __ballot_sync(0xFFFFFFFFu, sel);
        int pos = count + __popc(m & ((1u << lane) - 1u));
        if (sel) {
            tok[e * CT + pos] = t;
            etw[e * CT + pos] = w;
        }
        count += __popc(m);
    }
    if (lane == 0) cnt[e] = count;
    __syncthreads();
    if (threadIdx.x == 0) {
        int s = 0;
        for (int i = 0; i < CE; i++) { off[i] = s; s += cnt[i]; }
        off[CE] = s;
    }
}

// ---------------- GEGLU -> packed split (pairs along CI) ----------------
__global__ __launch_bounds__(256) void glu_kernel(
    const float* __restrict__ m1, const float* __restrict__ m2,
    uint32_t* __restrict__ oh, uint32_t* __restrict__ ol,
    const int* __restrict__ off)
{
    int row = blockIdx.y;
    if (row >= off[CE]) return;
    int p = blockIdx.x * 256 + threadIdx.x;      // 0..2047 k-pair index
    long base = (long)row * CI + 2 * p;
    float2 a = *(const float2*)&m1[base];
    float2 b = *(const float2*)&m2[base];
    float g0 = 0.5f * a.x * (1.0f + tanhf(0.7978845608028654f * (a.x + 0.044715f * a.x * a.x * a.x))) * b.x;
    float g1 = 0.5f * a.y * (1.0f + tanhf(0.7978845608028654f * (a.y + 0.044715f * a.y * a.y * a.y))) * b.y;
    uint32_t h, l;
    split_pack(g0, g1, h, l);
    oh[(long)row * 2048 + p] = h;
    ol[(long)row * 2048 + p] = l;
}

// ---------------- zero fill ----------------
__global__ __launch_bounds__(256) void zero_kernel(float* __restrict__ p)
{
    p[(long)blockIdx.x * 256 + threadIdx.x] = 0.f;
}

// ---------------- host orchestration ----------------
#define SYMADDR(var, ptr) do { void* _p = nullptr; cudaGetSymbolAddress(&_p, var); ptr = (decltype(ptr))_p; } while (0)

extern "C" void kernel_launch(void* const* d_in, const int* in_sizes, int n_in,
                              void* d_out, int out_size)
{
    const float* hidden   = (const float*)d_in[0];
    const int*   amask    = (const int*)d_in[1];
    const int*   posids   = (const int*)d_in[2];
    const float* q_w      = (const float*)d_in[3];
    const float* k_w      = (const float*)d_in[4];
    const float* v_w      = (const float*)d_in[5];
    const float* o_w      = (const float*)d_in[6];
    const float* pre_attn = (const float*)d_in[7];
    const float* post_attn= (const float*)d_in[8];
    const float* pre_moe  = (const float*)d_in[9];
    const float* post_moe = (const float*)d_in[10];
    const float* gate_w   = (const float*)d_in[11];
    const float* w_in     = (const float*)d_in[12];
    const float* w_v      = (const float*)d_in[13];
    const float* w_out    = (const float*)d_in[14];
    float* out = (float*)d_out;

    float *q, *k, *v, *aproj, *x, *h2, *mid1, *mid2, *moe, *topw, *etw;
    int *topi, *tok, *cnt, *off;
    uint32_t *hnh, *hnl, *ath, *atl, *h2h, *h2l, *m1h, *m1l;
    uint32_t *qwh, *qwl, *kwh, *kwl, *vwh, *vwl, *owh, *owl;
    uint32_t *wih, *wil, *wvh, *wvl, *woh, *wol;
    SYMADDR(g_q, q); SYMADDR(g_k, k); SYMADDR(g_v, v);
    SYMADDR(g_aproj, aproj); SYMADDR(g_x, x); SYMADDR(g_h2, h2);
    SYMADDR(g_mid1, mid1); SYMADDR(g_mid2, mid2); SYMADDR(g_moe, moe);
    SYMADDR(g_topi, topi); SYMADDR(g_topw, topw);
    SYMADDR(g_tok, tok); SYMADDR(g_etw, etw); SYMADDR(g_cnt, cnt); SYMADDR(g_off, off);
    SYMADDR(g_hnh, hnh); SYMADDR(g_hnl, hnl); SYMADDR(g_ath, ath); SYMADDR(g_atl, atl);
    SYMADDR(g_h2h, h2h); SYMADDR(g_h2l, h2l); SYMADDR(g_m1h, m1h); SYMADDR(g_m1l, m1l);
    SYMADDR(g_qwh, qwh); SYMADDR(g_qwl, qwl); SYMADDR(g_kwh, kwh); SYMADDR(g_kwl, kwl);
    SYMADDR(g_vwh, vwh); SYMADDR(g_vwl, vwl); SYMADDR(g_owh, owh); SYMADDR(g_owl, owl);
    SYMADDR(g_wih, wih); SYMADDR(g_wil, wil); SYMADDR(g_wvh, wvh); SYMADDR(g_wvl, wvl);
    SYMADDR(g_woh, woh); SYMADDR(g_wol, wol);

    cudaFuncSetAttribute((const void*)flash_attn_kernel,
                         cudaFuncAttributeMaxDynamicSharedMemorySize, FA_SMEM_BYTES);

    // 0) weight splits (bandwidth-bound, ~130us total)
    wconv_kernel<<<(int)((512L * 256 + 255) / 256), 256>>>(q_w, qwh, qwl, 512, 1024);
    wconv_kernel<<<(int)((512L * 64 + 255) / 256), 256>>>(k_w, kwh, kwl, 512, 256);
    wconv_kernel<<<(int)((512L * 64 + 255) / 256), 256>>>(v_w, vwh, vwl, 512, 256);
    wconv_kernel<<<(int)((512L * 256 + 255) / 256), 256>>>(o_w, owh, owl, 512, 1024);
    wconv_kernel<<<(int)((4096L * 1024 + 255) / 256), 256>>>(w_in, wih, wil, 8L * 512, 4096);
    wconv_kernel<<<(int)((4096L * 1024 + 255) / 256), 256>>>(w_v, wvh, wvl, 8L * 512, 4096);
    wconv_kernel<<<(int)((16384L * 256 + 255) / 256), 256>>>(w_out, woh, wol, 8L * 2048, 1024);

    // 1) pre-attn rmsnorm -> packed split only
    rmsnorm_kernel<<<CT, 256>>>(hidden, pre_attn, nullptr, nullptr, hnh, hnl);

    // 2) fused QKV projections
    qkv_kernel<<<dim3(12, CT / 128), 256>>>(hnh, hnl, qwh, qwl, kwh, kwl, vwh, vwl, q, k, v);

    // 3) RoPE
    rope_kernel<<<(CT * 20 * 32) / 256, 256>>>(q, k, posids);

    // 4) fused flash attention -> packed split attn
    flash_attn_kernel<<<dim3(CS / 64, CB * CNH), 256, FA_SMEM_BYTES>>>(
        q, k, v, amask, ath, atl);

    // 5) output projection + post-attn rmsnorm + residual
    oproj_kernel<<<dim3(CH / 128, CT / 128), 256>>>(ath, atl, owh, owl, aproj);
    rmsnorm_kernel<<<CT, 256>>>(aproj, post_attn, hidden, x, nullptr, nullptr);

    // 6) pre-moe rmsnorm -> fp32 (gate) + packed split (stage1)
    rmsnorm_kernel<<<CT, 256>>>(x, pre_moe, nullptr, h2, h2h, h2l);

    // 7) gating + routing
    gate_kernel<<<CT, 128>>>(h2, gate_w, topi, topw);
    route_kernel<<<1, 256>>>(topi, topw, tok, etw, cnt, off);

    // 8) sparse MoE
    zero_kernel<<<(CT * CH) / 256, 256>>>(moe);
    moe_stage1_kernel<<<dim3(CI / 128, CT / 128, CE * 2), 256>>>(
        h2h, h2l, wih, wil, wvh, wvl, mid1, mid2, tok, cnt, off);
    glu_kernel<<<dim3(CI / 512, CSLOTS), 256>>>(mid1, mid2, m1h, m1l, off);
    moe_stage2_kernel<<<dim3(CH / 128, CT / 128, CE), 256>>>(
        m1h, m1l, woh, wol, moe, tok, etw, cnt, off);

    // 9) post-moe rmsnorm + residual -> output
    rmsnorm_kernel<<<CT, 256>>>(moe, post_moe, x, out, nullptr, nullptr);
}